// round 3
// baseline (speedup 1.0000x reference)
#include <cuda_runtime.h>
#include <math.h>

// ---------------------------------------------------------------------------
// Problem constants
//   x:      (B=16, C=2048, H=16, W=8)  HW=128
//   vfeat:  (N=16, V=128, C=2048)
//   C8 = 256, G = 2
// Output: concat( y2 (16*2048*128), g (16*128*2048) ) fp32
// ---------------------------------------------------------------------------
#define BSZ   16
#define CCH   2048
#define HW    128
#define C8    256
#define NV    16
#define VV    128
#define GNUM  2

// ------------------------- scratch (device globals) ------------------------
__device__ __align__(256) float d_q   [BSZ * C8 * HW];
__device__ __align__(256) float d_k   [BSZ * C8 * HW];
__device__ __align__(256) float d_v   [BSZ * CCH * HW];
__device__ __align__(256) float d_att1[BSZ * HW * HW];
__device__ __align__(256) float d_y1  [BSZ * CCH * HW];
__device__ __align__(256) float d_h   [NV * VV * CCH];
__device__ __align__(256) float d_ip  [NV * VV * VV];
__device__ __align__(256) float d_graph[NV * VV * VV];
__device__ __align__(256) float d_hp  [NV * VV * CCH];
__device__ __align__(256) float d_gbuf[NV * VV * CCH];
__device__ __align__(256) float d_mean[CCH];
__device__ __align__(256) float d_var [CCH];

// ------------------------------ GEMM --------------------------------------
// C[b] = alpha * op(A[b]) @ op(B[b]) + bias[m] + Res[b]
#define BM 128
#define BN 128
#define BK 8

template<int TA, int TB>
__global__ __launch_bounds__(256)
void gemm_kernel(const float* __restrict__ Ag, const float* __restrict__ Bg,
                 float* __restrict__ Cg,
                 int M, int N, int K,
                 long sA, long sB, long sC,
                 const float* __restrict__ bias,
                 const float* __restrict__ Res, long sRes,
                 float alphaH, const float* __restrict__ alphaD)
{
    __shared__ float As[BK][BM + 4];
    __shared__ float Bs[BK][BN + 4];

    const int bz = blockIdx.z;
    const float* A = Ag + (long)bz * sA;
    const float* B = Bg + (long)bz * sB;
    float*       C = Cg + (long)bz * sC;

    const int m0 = blockIdx.y * BM;
    const int n0 = blockIdx.x * BN;
    const int tid = threadIdx.x;
    const int tr = tid >> 4;      // 0..15
    const int tc = tid & 15;      // 0..15

    float acc[8][8];
#pragma unroll
    for (int i = 0; i < 8; i++)
#pragma unroll
        for (int j = 0; j < 8; j++) acc[i][j] = 0.f;

    for (int k0 = 0; k0 < K; k0 += BK) {
        if (TA == 0) {
#pragma unroll
            for (int i = tid; i < BM * BK; i += 256) {
                int m = i >> 3, kk = i & 7;
                As[kk][m] = __ldg(&A[(long)(m0 + m) * K + k0 + kk]);
            }
        } else {
#pragma unroll
            for (int i = tid; i < BM * BK; i += 256) {
                int kk = i >> 7, m = i & 127;
                As[kk][m] = __ldg(&A[(long)(k0 + kk) * M + m0 + m]);
            }
        }
        if (TB == 0) {
#pragma unroll
            for (int i = tid; i < BN * BK; i += 256) {
                int kk = i >> 7, n = i & 127;
                Bs[kk][n] = __ldg(&B[(long)(k0 + kk) * N + n0 + n]);
            }
        } else {
#pragma unroll
            for (int i = tid; i < BN * BK; i += 256) {
                int n = i >> 3, kk = i & 7;
                Bs[kk][n] = __ldg(&B[(long)(n0 + n) * K + k0 + kk]);
            }
        }
        __syncthreads();

#pragma unroll
        for (int kk = 0; kk < BK; kk++) {
            float a[8], b[8];
            *(float4*)&a[0] = *(const float4*)&As[kk][tr * 4];
            *(float4*)&a[4] = *(const float4*)&As[kk][64 + tr * 4];
            *(float4*)&b[0] = *(const float4*)&Bs[kk][tc * 4];
            *(float4*)&b[4] = *(const float4*)&Bs[kk][64 + tc * 4];
#pragma unroll
            for (int i = 0; i < 8; i++)
#pragma unroll
                for (int j = 0; j < 8; j++)
                    acc[i][j] += a[i] * b[j];
        }
        __syncthreads();
    }

    const float alpha = alphaD ? *alphaD : alphaH;

#pragma unroll
    for (int ig = 0; ig < 2; ig++) {
#pragma unroll
        for (int ii = 0; ii < 4; ii++) {
            const int i = ig * 4 + ii;
            const int m = m0 + ig * 64 + tr * 4 + ii;
            const float bi = bias ? __ldg(&bias[m]) : 0.f;
#pragma unroll
            for (int jg = 0; jg < 2; jg++) {
                const int n = n0 + jg * 64 + tc * 4;
                const long off = (long)m * N + n;
                float4 o;
                o.x = alpha * acc[i][jg * 4 + 0] + bi;
                o.y = alpha * acc[i][jg * 4 + 1] + bi;
                o.z = alpha * acc[i][jg * 4 + 2] + bi;
                o.w = alpha * acc[i][jg * 4 + 3] + bi;
                if (Res) {
                    float4 r = *(const float4*)&Res[(long)bz * sRes + off];
                    o.x += r.x; o.y += r.y; o.z += r.z; o.w += r.w;
                }
                *(float4*)&C[off] = o;
            }
        }
    }
}

// --------------------------- reductions ------------------------------------
__device__ __forceinline__ float warpMax(float v) {
#pragma unroll
    for (int o = 16; o; o >>= 1) v = fmaxf(v, __shfl_xor_sync(0xffffffffu, v, o));
    return v;
}
__device__ __forceinline__ float warpSum(float v) {
#pragma unroll
    for (int o = 16; o; o >>= 1) v += __shfl_xor_sync(0xffffffffu, v, o);
    return v;
}
// reductions within 16-lane groups (threads sharing the same micro-row)
__device__ __forceinline__ float red16max(float v) {
#pragma unroll
    for (int o = 8; o; o >>= 1) v = fmaxf(v, __shfl_xor_sync(0xffffffffu, v, o));
    return v;
}
__device__ __forceinline__ float red16sum(float v) {
#pragma unroll
    for (int o = 8; o; o >>= 1) v += __shfl_xor_sync(0xffffffffu, v, o);
    return v;
}

// in-place row softmax; one block per row
__global__ void softmax_kernel(float* __restrict__ d, int ncols)
{
    __shared__ float red[32];
    __shared__ float bcast;
    const long row = blockIdx.x;
    float* p = d + row * (long)ncols;
    const int tid = threadIdx.x, nt = blockDim.x;

    float m = -1e30f;
    for (int i = tid; i < ncols; i += nt) m = fmaxf(m, p[i]);
    m = warpMax(m);
    if ((tid & 31) == 0) red[tid >> 5] = m;
    __syncthreads();
    if (tid < 32) {
        float v = (tid < (nt >> 5)) ? red[tid] : -1e30f;
        v = warpMax(v);
        if (tid == 0) bcast = v;
    }
    __syncthreads();
    m = bcast;

    float s = 0.f;
    for (int i = tid; i < ncols; i += nt) {
        float e = __expf(p[i] - m);
        p[i] = e;
        s += e;
    }
    __syncthreads();
    s = warpSum(s);
    if ((tid & 31) == 0) red[tid >> 5] = s;
    __syncthreads();
    if (tid < 32) {
        float v = (tid < (nt >> 5)) ? red[tid] : 0.f;
        v = warpSum(v);
        if (tid == 0) bcast = v;
    }
    __syncthreads();
    const float inv = 1.f / bcast;
    for (int i = tid; i < ncols; i += nt) p[i] *= inv;
}

// --------------------- fused CAM (flash-attention style) -------------------
// Q = K = V = rows of y1[b] (2048 x 128). scores = -(Q @ K^T).
// out = gamma * softmax(scores) @ V + y1, written directly to d_out half 1.
// Block: 64 query rows; streams 16 K/V tiles of 128 rows. 256 threads.
#define CAM_BR   64
#define CAM_BC   128
#define CAM_QP   68     // Qst pitch  [128][68]  (Q transposed: [m][r])
#define CAM_KTP  132    // Kts pitch  [128][132] (K transposed: [m][d])
#define CAM_KSP  128    // Ks  pitch  [128][128] (K/V natural:  [d][m])
#define CAM_PP   68     // Pt  pitch  [128][68]  (P transposed: [d][r])
#define CAM_SMEM ((128*CAM_QP + 128*CAM_KTP + 128*CAM_KSP + 128*CAM_PP) * 4)

__global__ __launch_bounds__(256)
void cam_fused_kernel(const float* __restrict__ y1g,
                      const float* __restrict__ gptr,
                      float* __restrict__ outg)
{
    extern __shared__ float sm[];
    float* Qst = sm;                       // [m][r]
    float* Kts = Qst + 128 * CAM_QP;       // [m][d]
    float* Ks  = Kts + 128 * CAM_KTP;      // [d][m]
    float* Pt  = Ks  + 128 * CAM_KSP;      // [d][r]

    const int b  = blockIdx.y;
    const int c0 = blockIdx.x * CAM_BR;
    const float* Y = y1g + (long)b * CCH * HW;

    const int tid = threadIdx.x;
    const int tr  = tid >> 4;    // 0..15 -> rows tr*4..tr*4+3
    const int tc  = tid & 15;    // 0..15 -> cols {tc*4+j, 64+tc*4+j}

    // load Q tile transposed: Qst[m][r] = Y[c0+r][m]
    for (int i = tid; i < CAM_BR * 128; i += 256) {
        int r = i >> 7, m = i & 127;
        Qst[m * CAM_QP + r] = Y[(long)(c0 + r) * HW + m];
    }

    float acc[4][8];
    float mrow[4], lrow[4];
#pragma unroll
    for (int i = 0; i < 4; i++) {
        mrow[i] = -1e30f; lrow[i] = 0.f;
#pragma unroll
        for (int j = 0; j < 8; j++) acc[i][j] = 0.f;
    }

    for (int t = 0; t < CCH / CAM_BC; t++) {
        const int d0 = t * CAM_BC;
        __syncthreads();   // Q ready (t=0) / previous PV done
        // load K tile in both layouts
        for (int i = tid; i < CAM_BC * 128; i += 256) {
            int d = i >> 7, m = i & 127;
            float v = Y[(long)(d0 + d) * HW + m];
            Ks [d * CAM_KSP + m] = v;
            Kts[m * CAM_KTP + d] = v;
        }
        __syncthreads();

        // S = Q @ K^T (positive dot; score = -S)
        float s[4][8];
#pragma unroll
        for (int i = 0; i < 4; i++)
#pragma unroll
            for (int j = 0; j < 8; j++) s[i][j] = 0.f;

#pragma unroll 4
        for (int kk = 0; kk < 128; kk++) {
            float a[4], bb[8];
            *(float4*)&a[0]  = *(const float4*)&Qst[kk * CAM_QP + tr * 4];
            *(float4*)&bb[0] = *(const float4*)&Kts[kk * CAM_KTP + tc * 4];
            *(float4*)&bb[4] = *(const float4*)&Kts[kk * CAM_KTP + 64 + tc * 4];
#pragma unroll
            for (int i = 0; i < 4; i++)
#pragma unroll
                for (int j = 0; j < 8; j++)
                    s[i][j] += a[i] * bb[j];
        }

        // online softmax (scores = -s), P written into s[][]
#pragma unroll
        for (int rr = 0; rr < 4; rr++) {
            float mx = -1e30f;
#pragma unroll
            for (int j = 0; j < 8; j++) mx = fmaxf(mx, -s[rr][j]);
            mx = red16max(mx);
            float mnew  = fmaxf(mrow[rr], mx);
            float scale = __expf(mrow[rr] - mnew);
            float rs = 0.f;
#pragma unroll
            for (int j = 0; j < 8; j++) {
                float p = __expf(-s[rr][j] - mnew);
                s[rr][j] = p;
                rs += p;
            }
            rs = red16sum(rs);
            lrow[rr] = lrow[rr] * scale + rs;
            mrow[rr] = mnew;
#pragma unroll
            for (int j = 0; j < 8; j++) acc[rr][j] *= scale;
        }

        // stage P transposed: Pt[d][r]
#pragma unroll
        for (int rr = 0; rr < 4; rr++) {
#pragma unroll
            for (int j = 0; j < 8; j++) {
                int dl = (j < 4) ? (tc * 4 + j) : (64 + tc * 4 + (j - 4));
                Pt[dl * CAM_PP + tr * 4 + rr] = s[rr][j];
            }
        }
        __syncthreads();

        // acc += P @ V  (V = Ks)
#pragma unroll 4
        for (int kk = 0; kk < 128; kk++) {
            float a[4], bb[8];
            *(float4*)&a[0]  = *(const float4*)&Pt[kk * CAM_PP + tr * 4];
            *(float4*)&bb[0] = *(const float4*)&Ks[kk * CAM_KSP + tc * 4];
            *(float4*)&bb[4] = *(const float4*)&Ks[kk * CAM_KSP + 64 + tc * 4];
#pragma unroll
            for (int i = 0; i < 4; i++)
#pragma unroll
                for (int j = 0; j < 8; j++)
                    acc[i][j] += a[i] * bb[j];
        }
    }

    // epilogue: out = gamma * acc / l + y1
    const float g = *gptr;
    float* O = outg + (long)b * CCH * HW;
#pragma unroll
    for (int rr = 0; rr < 4; rr++) {
        const int r = tr * 4 + rr;
        const float inv = g / lrow[rr];
#pragma unroll
        for (int jg = 0; jg < 2; jg++) {
            const int n = jg * 64 + tc * 4;
            const long off = (long)(c0 + r) * HW + n;
            float4 yv = *(const float4*)&Y[off];
            float4 o;
            o.x = acc[rr][jg * 4 + 0] * inv + yv.x;
            o.y = acc[rr][jg * 4 + 1] * inv + yv.y;
            o.z = acc[rr][jg * 4 + 2] * inv + yv.z;
            o.w = acc[rr][jg * 4 + 3] * inv + yv.w;
            *(float4*)&O[off] = o;
        }
    }
}

// ------------------------ graph construction -------------------------------
__global__ void graph_build(const float* __restrict__ ip,
                            const float* __restrict__ adj,
                            float* __restrict__ graph)
{
    __shared__ float reda[4], redb[4];
    const int n = blockIdx.y, v = blockIdx.x, w = threadIdx.x;
    const long base = ((long)n * VV + v) * VV;

    const float sqv = ip[((long)n * VV + v) * VV + v];
    const float sqw = ip[((long)n * VV + w) * VV + w];
    const float e   = ip[base + w];

    float d2   = sqv + sqw - 2.f * e;
    float dist = sqrtf(fmaxf(d2, 1e-12f));
    float sim  = 2.f / (expf(dist) + 1.f);
    float av   = adj[base + w];
    if (w == v) { sim = 0.f; av = 0.f; }

    float s1 = warpSum(fabsf(sim));
    float s2 = warpSum(fabsf(av));
    if ((w & 31) == 0) { reda[w >> 5] = s1; redb[w >> 5] = s2; }
    __syncthreads();
    const float ssum = reda[0] + reda[1] + reda[2] + reda[3];
    const float asum = redb[0] + redb[1] + redb[2] + redb[3];

    graph[base + w] = 0.5f * (av / fmaxf(asum, 1e-12f) + sim / fmaxf(ssum, 1e-12f));
}

// ------------------------- batch-norm stats --------------------------------
__global__ void bn_stats(const float* __restrict__ hp,
                         float* __restrict__ mean, float* __restrict__ var,
                         int rows, int C)
{
    __shared__ float shs[8][32];
    __shared__ float shs2[8][32];
    const int lane = threadIdx.x & 31;
    const int ry   = threadIdx.x >> 5;
    const int c    = blockIdx.x * 32 + lane;

    float s = 0.f, s2 = 0.f;
    for (int r = ry; r < rows; r += 8) {
        float v = hp[(long)r * C + c];
        s += v; s2 += v * v;
    }
    shs[ry][lane] = s; shs2[ry][lane] = s2;
    __syncthreads();
    if (ry == 0) {
#pragma unroll
        for (int j = 1; j < 8; j++) { s += shs[j][lane]; s2 += shs2[j][lane]; }
        float mu = s / rows;
        mean[c] = mu;
        var[c]  = s2 / rows - mu * mu;
    }
}

// ------------------- BN apply + LeakyReLU + residual -----------------------
__global__ void bn_apply(const float* __restrict__ inp,
                         const float* __restrict__ hp,
                         const float* __restrict__ mean,
                         const float* __restrict__ var,
                         const float* __restrict__ bw,
                         const float* __restrict__ bb,
                         const float* __restrict__ gptr,
                         float* __restrict__ out, int total, int C)
{
    const int idx = blockIdx.x * blockDim.x + threadIdx.x;
    if (idx >= total) return;
    const int c = idx & (C - 1);
    const float g = *gptr;
    float vv = (hp[idx] - mean[c]) * rsqrtf(var[c] + 1e-5f) * bw[c] + bb[c];
    float lr = vv > 0.f ? vv : 0.1f * vv;
    out[idx] = inp[idx] + g * lr;
}

// ------------------------------ host side ----------------------------------
static void launch_gemm(int TA, int TB,
                        const float* A, const float* B, float* C,
                        int M, int N, int K,
                        long sA, long sB, long sC, int batch,
                        const float* bias,
                        const float* Res, long sRes,
                        float aH, const float* aD)
{
    dim3 grid(N / BN, M / BM, batch);
    dim3 blk(256);
    if (TA == 0 && TB == 0)
        gemm_kernel<0, 0><<<grid, blk>>>(A, B, C, M, N, K, sA, sB, sC, bias, Res, sRes, aH, aD);
    else if (TA == 1 && TB == 0)
        gemm_kernel<1, 0><<<grid, blk>>>(A, B, C, M, N, K, sA, sB, sC, bias, Res, sRes, aH, aD);
    else
        gemm_kernel<0, 1><<<grid, blk>>>(A, B, C, M, N, K, sA, sB, sC, bias, Res, sRes, aH, aD);
}

extern "C" void kernel_launch(void* const* d_in, const int* in_sizes, int n_in,
                              void* d_out, int out_size)
{
    const float* x     = (const float*)d_in[0];
    const float* vfeat = (const float*)d_in[1];
    const float* adj   = (const float*)d_in[2];
    const float* Wq    = (const float*)d_in[3];
    const float* bq    = (const float*)d_in[4];
    const float* Wk    = (const float*)d_in[5];
    const float* bk    = (const float*)d_in[6];
    const float* Wv    = (const float*)d_in[7];
    const float* bv    = (const float*)d_in[8];
    const float* gpam  = (const float*)d_in[9];
    const float* gcam  = (const float*)d_in[10];
    const float* Wg    = (const float*)d_in[11];
    const float* bnw   = (const float*)d_in[12];
    const float* bnb   = (const float*)d_in[13];
    const float* gg    = (const float*)d_in[14];
    float* out = (float*)d_out;

    float *q, *k, *v, *att1, *y1, *h, *ip, *graph, *hp, *gbuf, *mean, *var;
    cudaGetSymbolAddress((void**)&q,    d_q);
    cudaGetSymbolAddress((void**)&k,    d_k);
    cudaGetSymbolAddress((void**)&v,    d_v);
    cudaGetSymbolAddress((void**)&att1, d_att1);
    cudaGetSymbolAddress((void**)&y1,   d_y1);
    cudaGetSymbolAddress((void**)&h,    d_h);
    cudaGetSymbolAddress((void**)&ip,   d_ip);
    cudaGetSymbolAddress((void**)&graph,d_graph);
    cudaGetSymbolAddress((void**)&hp,   d_hp);
    cudaGetSymbolAddress((void**)&gbuf, d_gbuf);
    cudaGetSymbolAddress((void**)&mean, d_mean);
    cudaGetSymbolAddress((void**)&var,  d_var);

    static int smem_set = 0;
    if (!smem_set) {
        cudaFuncSetAttribute(cam_fused_kernel,
                             cudaFuncAttributeMaxDynamicSharedMemorySize, CAM_SMEM);
        smem_set = 1;
    }

    const long CHW = (long)CCH * HW;          // 262144
    const long QHW = (long)C8 * HW;           // 32768
    const long GST = (long)VV * CCH;          // 262144

    // ---------------- PAM ----------------
    launch_gemm(0, 0, Wq, x, q, C8,  HW, CCH, 0, CHW, QHW, BSZ, bq, nullptr, 0, 1.f, nullptr);
    launch_gemm(0, 0, Wk, x, k, C8,  HW, CCH, 0, CHW, QHW, BSZ, bk, nullptr, 0, 1.f, nullptr);
    launch_gemm(0, 0, Wv, x, v, CCH, HW, CCH, 0, CHW, CHW, BSZ, bv, nullptr, 0, 1.f, nullptr);
    launch_gemm(1, 0, q, k, att1, HW, HW, C8, QHW, QHW, (long)HW * HW, BSZ,
                nullptr, nullptr, 0, 1.f, nullptr);
    softmax_kernel<<<BSZ * HW, 128>>>(att1, HW);
    launch_gemm(0, 1, v, att1, y1, CCH, HW, HW, CHW, (long)HW * HW, CHW, BSZ,
                nullptr, x, CHW, 0.f, gpam);

    // ---------------- CAM (fused flash-style) ----------------
    {
        dim3 grid(CCH / CAM_BR, BSZ);
        cam_fused_kernel<<<grid, 256, CAM_SMEM>>>(y1, gcam, out);
    }

    // ------------- Graph layers -------------
    const float* inp = vfeat;
    for (int i = 0; i < GNUM; i++) {
        float* outg = (i == GNUM - 1) ? (out + (long)BSZ * CCH * HW) : gbuf;
        launch_gemm(0, 1, inp, Wg + (long)i * CCH * CCH, h,
                    NV * VV, CCH, CCH, 0, 0, 0, 1, nullptr, nullptr, 0, 1.f, nullptr);
        launch_gemm(0, 1, inp, inp, ip, VV, VV, CCH, GST, GST, (long)VV * VV, NV,
                    nullptr, nullptr, 0, 1.f, nullptr);
        graph_build<<<dim3(VV, NV), VV>>>(ip, adj, graph);
        launch_gemm(0, 0, graph, h, hp, VV, CCH, VV, (long)VV * VV, GST, GST, NV,
                    nullptr, nullptr, 0, 1.f, nullptr);
        bn_stats<<<CCH / 32, 256>>>(hp, mean, var, NV * VV, CCH);
        bn_apply<<<(NV * VV * CCH + 255) / 256, 256>>>(
            inp, hp, mean, var, bnw + (long)i * CCH, bnb + (long)i * CCH,
            gg + i, outg, NV * VV * CCH, CCH);
        inp = outg;
    }
}

// round 4
// speedup vs baseline: 1.4240x; 1.4240x over previous
#include <cuda_runtime.h>
#include <math.h>

// ---------------------------------------------------------------------------
// Problem constants
// ---------------------------------------------------------------------------
#define BSZ   16
#define CCH   2048
#define HW    128
#define C8    256
#define NV    16
#define VV    128
#define GNUM  2

// ------------------------- scratch (device globals) ------------------------
__device__ __align__(256) float d_q   [BSZ * C8 * HW];
__device__ __align__(256) float d_k   [BSZ * C8 * HW];
__device__ __align__(256) float d_v   [BSZ * CCH * HW];
__device__ __align__(256) float d_att1[BSZ * HW * HW];
__device__ __align__(256) float d_y1  [BSZ * CCH * HW];
__device__ __align__(256) float d_h   [NV * VV * CCH];
__device__ __align__(256) float d_ip  [NV * VV * VV];
__device__ __align__(256) float d_graph[NV * VV * VV];
__device__ __align__(256) float d_hp  [NV * VV * CCH];
__device__ __align__(256) float d_gbuf[NV * VV * CCH];
__device__ __align__(256) float d_mean[CCH];
__device__ __align__(256) float d_var [CCH];

// ------------------------------ GEMM v2 ------------------------------------
// C[b] = alpha * op(A[b]) @ op(B[b]) + bias[m] + Res[b]
// 128x128 tile, BK=16, double-buffered smem, 256 threads, 8x8 micro.
// TA==0: A is MxK row-major;  TA==1: A is KxM row-major
// TB==0: B is KxN row-major;  TB==1: B is NxK row-major
#define GBK 16

template<int TA, int TB>
__global__ __launch_bounds__(256, 2)
void gemm_kernel(const float* __restrict__ Ag, const float* __restrict__ Bg,
                 float* __restrict__ Cg,
                 int M, int N, int K,
                 long sA, long sB, long sC,
                 const float* __restrict__ bias,
                 const float* __restrict__ Res, long sRes,
                 float alphaH, const float* __restrict__ alphaD)
{
    __shared__ __align__(16) float As[2][GBK][132];
    __shared__ __align__(16) float Bs[2][GBK][132];

    const int bz = blockIdx.z;
    const float* A = Ag + (long)bz * sA;
    const float* B = Bg + (long)bz * sB;
    float*       C = Cg + (long)bz * sC;

    const int m0 = blockIdx.y * 128;
    const int n0 = blockIdx.x * 128;
    const int tid = threadIdx.x;
    const int tr = tid >> 4;      // 0..15
    const int tc = tid & 15;      // 0..15

    // prefetch addressing
    const int lr  = tid >> 2;          // 0..63   (transpose-load path)
    const int lc  = (tid & 3) * 4;     // 0,4,8,12
    const int kk8 = tid >> 5;          // 0..7    (direct-load path)
    const int nf  = (tid & 31) * 4;    // 0..124

    float4 pa0, pa1, pb0, pb1;

    float acc[8][8];
#pragma unroll
    for (int i = 0; i < 8; i++)
#pragma unroll
        for (int j = 0; j < 8; j++) acc[i][j] = 0.f;

    const int nt = K / GBK;

    // ---- load helpers (macros keep one code path per template) ----
#define LOAD_A(k0)                                                         \
    do {                                                                   \
        if (TA == 0) {                                                     \
            pa0 = *(const float4*)&A[(long)(m0 + lr) * K + (k0) + lc];     \
            pa1 = *(const float4*)&A[(long)(m0 + lr + 64) * K + (k0) + lc];\
        } else {                                                           \
            pa0 = *(const float4*)&A[(long)((k0) + kk8) * M + m0 + nf];    \
            pa1 = *(const float4*)&A[(long)((k0) + kk8 + 8) * M + m0 + nf];\
        }                                                                  \
    } while (0)

#define LOAD_B(k0)                                                         \
    do {                                                                   \
        if (TB == 0) {                                                     \
            pb0 = *(const float4*)&B[(long)((k0) + kk8) * N + n0 + nf];    \
            pb1 = *(const float4*)&B[(long)((k0) + kk8 + 8) * N + n0 + nf];\
        } else {                                                           \
            pb0 = *(const float4*)&B[(long)(n0 + lr) * K + (k0) + lc];     \
            pb1 = *(const float4*)&B[(long)(n0 + lr + 64) * K + (k0) + lc];\
        }                                                                  \
    } while (0)

#define STORE_A(bf)                                                        \
    do {                                                                   \
        if (TA == 0) {                                                     \
            As[bf][lc + 0][lr] = pa0.x; As[bf][lc + 1][lr] = pa0.y;        \
            As[bf][lc + 2][lr] = pa0.z; As[bf][lc + 3][lr] = pa0.w;        \
            As[bf][lc + 0][lr + 64] = pa1.x; As[bf][lc + 1][lr + 64] = pa1.y; \
            As[bf][lc + 2][lr + 64] = pa1.z; As[bf][lc + 3][lr + 64] = pa1.w; \
        } else {                                                           \
            *(float4*)&As[bf][kk8][nf]     = pa0;                          \
            *(float4*)&As[bf][kk8 + 8][nf] = pa1;                          \
        }                                                                  \
    } while (0)

#define STORE_B(bf)                                                        \
    do {                                                                   \
        if (TB == 0) {                                                     \
            *(float4*)&Bs[bf][kk8][nf]     = pb0;                          \
            *(float4*)&Bs[bf][kk8 + 8][nf] = pb1;                          \
        } else {                                                           \
            Bs[bf][lc + 0][lr] = pb0.x; Bs[bf][lc + 1][lr] = pb0.y;        \
            Bs[bf][lc + 2][lr] = pb0.z; Bs[bf][lc + 3][lr] = pb0.w;        \
            Bs[bf][lc + 0][lr + 64] = pb1.x; Bs[bf][lc + 1][lr + 64] = pb1.y; \
            Bs[bf][lc + 2][lr + 64] = pb1.z; Bs[bf][lc + 3][lr + 64] = pb1.w; \
        }                                                                  \
    } while (0)

    LOAD_A(0); LOAD_B(0);
    STORE_A(0); STORE_B(0);
    __syncthreads();

    int buf = 0;
    for (int t = 0; t < nt; t++) {
        if (t + 1 < nt) { LOAD_A((t + 1) * GBK); LOAD_B((t + 1) * GBK); }

#pragma unroll
        for (int kk = 0; kk < GBK; kk++) {
            float a[8], b[8];
            *(float4*)&a[0] = *(const float4*)&As[buf][kk][tr * 4];
            *(float4*)&a[4] = *(const float4*)&As[buf][kk][64 + tr * 4];
            *(float4*)&b[0] = *(const float4*)&Bs[buf][kk][tc * 4];
            *(float4*)&b[4] = *(const float4*)&Bs[buf][kk][64 + tc * 4];
#pragma unroll
            for (int i = 0; i < 8; i++)
#pragma unroll
                for (int j = 0; j < 8; j++)
                    acc[i][j] += a[i] * b[j];
        }

        if (t + 1 < nt) {
            STORE_A(buf ^ 1); STORE_B(buf ^ 1);
            __syncthreads();
            buf ^= 1;
        }
    }

    const float alpha = alphaD ? *alphaD : alphaH;

#pragma unroll
    for (int ig = 0; ig < 2; ig++) {
#pragma unroll
        for (int ii = 0; ii < 4; ii++) {
            const int i = ig * 4 + ii;
            const int m = m0 + ig * 64 + tr * 4 + ii;
            const float bi = bias ? __ldg(&bias[m]) : 0.f;
#pragma unroll
            for (int jg = 0; jg < 2; jg++) {
                const int n = n0 + jg * 64 + tc * 4;
                const long off = (long)m * N + n;
                float4 o;
                o.x = alpha * acc[i][jg * 4 + 0] + bi;
                o.y = alpha * acc[i][jg * 4 + 1] + bi;
                o.z = alpha * acc[i][jg * 4 + 2] + bi;
                o.w = alpha * acc[i][jg * 4 + 3] + bi;
                if (Res) {
                    float4 r = *(const float4*)&Res[(long)bz * sRes + off];
                    o.x += r.x; o.y += r.y; o.z += r.z; o.w += r.w;
                }
                *(float4*)&C[off] = o;
            }
        }
    }
#undef LOAD_A
#undef LOAD_B
#undef STORE_A
#undef STORE_B
}

// --------------------------- reductions ------------------------------------
__device__ __forceinline__ float warpMax(float v) {
#pragma unroll
    for (int o = 16; o; o >>= 1) v = fmaxf(v, __shfl_xor_sync(0xffffffffu, v, o));
    return v;
}
__device__ __forceinline__ float warpSum(float v) {
#pragma unroll
    for (int o = 16; o; o >>= 1) v += __shfl_xor_sync(0xffffffffu, v, o);
    return v;
}
__device__ __forceinline__ float red16max(float v) {
#pragma unroll
    for (int o = 8; o; o >>= 1) v = fmaxf(v, __shfl_xor_sync(0xffffffffu, v, o));
    return v;
}
__device__ __forceinline__ float red16sum(float v) {
#pragma unroll
    for (int o = 8; o; o >>= 1) v += __shfl_xor_sync(0xffffffffu, v, o);
    return v;
}

// in-place row softmax; one block per row
__global__ void softmax_kernel(float* __restrict__ d, int ncols)
{
    __shared__ float red[32];
    __shared__ float bcast;
    const long row = blockIdx.x;
    float* p = d + row * (long)ncols;
    const int tid = threadIdx.x, nt = blockDim.x;

    float m = -1e30f;
    for (int i = tid; i < ncols; i += nt) m = fmaxf(m, p[i]);
    m = warpMax(m);
    if ((tid & 31) == 0) red[tid >> 5] = m;
    __syncthreads();
    if (tid < 32) {
        float v = (tid < (nt >> 5)) ? red[tid] : -1e30f;
        v = warpMax(v);
        if (tid == 0) bcast = v;
    }
    __syncthreads();
    m = bcast;

    float s = 0.f;
    for (int i = tid; i < ncols; i += nt) {
        float e = __expf(p[i] - m);
        p[i] = e;
        s += e;
    }
    __syncthreads();
    s = warpSum(s);
    if ((tid & 31) == 0) red[tid >> 5] = s;
    __syncthreads();
    if (tid < 32) {
        float v = (tid < (nt >> 5)) ? red[tid] : 0.f;
        v = warpSum(v);
        if (tid == 0) bcast = v;
    }
    __syncthreads();
    const float inv = 1.f / bcast;
    for (int i = tid; i < ncols; i += nt) p[i] *= inv;
}

// --------------------- fused CAM (flash-attention style) -------------------
#define CAM_BR   64
#define CAM_BC   128
#define CAM_QP   68
#define CAM_KTP  132
#define CAM_KSP  128
#define CAM_PP   68
#define CAM_SMEM ((128*CAM_QP + 128*CAM_KTP + 128*CAM_KSP + 128*CAM_PP) * 4)

__global__ __launch_bounds__(256)
void cam_fused_kernel(const float* __restrict__ y1g,
                      const float* __restrict__ gptr,
                      float* __restrict__ outg)
{
    extern __shared__ float sm[];
    float* Qst = sm;                       // [m][r]
    float* Kts = Qst + 128 * CAM_QP;       // [m][d]
    float* Ks  = Kts + 128 * CAM_KTP;      // [d][m]
    float* Pt  = Ks  + 128 * CAM_KSP;      // [d][r]

    const int b  = blockIdx.y;
    const int c0 = blockIdx.x * CAM_BR;
    const float* Y = y1g + (long)b * CCH * HW;

    const int tid = threadIdx.x;
    const int tr  = tid >> 4;
    const int tc  = tid & 15;

    for (int i = tid; i < CAM_BR * 128; i += 256) {
        int r = i >> 7, m = i & 127;
        Qst[m * CAM_QP + r] = Y[(long)(c0 + r) * HW + m];
    }

    float acc[4][8];
    float mrow[4], lrow[4];
#pragma unroll
    for (int i = 0; i < 4; i++) {
        mrow[i] = -1e30f; lrow[i] = 0.f;
#pragma unroll
        for (int j = 0; j < 8; j++) acc[i][j] = 0.f;
    }

    for (int t = 0; t < CCH / CAM_BC; t++) {
        const int d0 = t * CAM_BC;
        __syncthreads();
        for (int i = tid; i < CAM_BC * 128; i += 256) {
            int d = i >> 7, m = i & 127;
            float v = Y[(long)(d0 + d) * HW + m];
            Ks [d * CAM_KSP + m] = v;
            Kts[m * CAM_KTP + d] = v;
        }
        __syncthreads();

        float s[4][8];
#pragma unroll
        for (int i = 0; i < 4; i++)
#pragma unroll
            for (int j = 0; j < 8; j++) s[i][j] = 0.f;

#pragma unroll 4
        for (int kk = 0; kk < 128; kk++) {
            float a[4], bb[8];
            *(float4*)&a[0]  = *(const float4*)&Qst[kk * CAM_QP + tr * 4];
            *(float4*)&bb[0] = *(const float4*)&Kts[kk * CAM_KTP + tc * 4];
            *(float4*)&bb[4] = *(const float4*)&Kts[kk * CAM_KTP + 64 + tc * 4];
#pragma unroll
            for (int i = 0; i < 4; i++)
#pragma unroll
                for (int j = 0; j < 8; j++)
                    s[i][j] += a[i] * bb[j];
        }

#pragma unroll
        for (int rr = 0; rr < 4; rr++) {
            float mx = -1e30f;
#pragma unroll
            for (int j = 0; j < 8; j++) mx = fmaxf(mx, -s[rr][j]);
            mx = red16max(mx);
            float mnew  = fmaxf(mrow[rr], mx);
            float scale = __expf(mrow[rr] - mnew);
            float rs = 0.f;
#pragma unroll
            for (int j = 0; j < 8; j++) {
                float p = __expf(-s[rr][j] - mnew);
                s[rr][j] = p;
                rs += p;
            }
            rs = red16sum(rs);
            lrow[rr] = lrow[rr] * scale + rs;
            mrow[rr] = mnew;
#pragma unroll
            for (int j = 0; j < 8; j++) acc[rr][j] *= scale;
        }

#pragma unroll
        for (int rr = 0; rr < 4; rr++) {
#pragma unroll
            for (int j = 0; j < 8; j++) {
                int dl = (j < 4) ? (tc * 4 + j) : (64 + tc * 4 + (j - 4));
                Pt[dl * CAM_PP + tr * 4 + rr] = s[rr][j];
            }
        }
        __syncthreads();

#pragma unroll 4
        for (int kk = 0; kk < 128; kk++) {
            float a[4], bb[8];
            *(float4*)&a[0]  = *(const float4*)&Pt[kk * CAM_PP + tr * 4];
            *(float4*)&bb[0] = *(const float4*)&Ks[kk * CAM_KSP + tc * 4];
            *(float4*)&bb[4] = *(const float4*)&Ks[kk * CAM_KSP + 64 + tc * 4];
#pragma unroll
            for (int i = 0; i < 4; i++)
#pragma unroll
                for (int j = 0; j < 8; j++)
                    acc[i][j] += a[i] * bb[j];
        }
    }

    const float g = *gptr;
    float* O = outg + (long)b * CCH * HW;
#pragma unroll
    for (int rr = 0; rr < 4; rr++) {
        const int r = tr * 4 + rr;
        const float inv = g / lrow[rr];
#pragma unroll
        for (int jg = 0; jg < 2; jg++) {
            const int n = jg * 64 + tc * 4;
            const long off = (long)(c0 + r) * HW + n;
            float4 yv = *(const float4*)&Y[off];
            float4 o;
            o.x = acc[rr][jg * 4 + 0] * inv + yv.x;
            o.y = acc[rr][jg * 4 + 1] * inv + yv.y;
            o.z = acc[rr][jg * 4 + 2] * inv + yv.z;
            o.w = acc[rr][jg * 4 + 3] * inv + yv.w;
            *(float4*)&O[off] = o;
        }
    }
}

// ------------------------ graph construction -------------------------------
__global__ void graph_build(const float* __restrict__ ip,
                            const float* __restrict__ adj,
                            float* __restrict__ graph)
{
    __shared__ float reda[4], redb[4];
    const int n = blockIdx.y, v = blockIdx.x, w = threadIdx.x;
    const long base = ((long)n * VV + v) * VV;

    const float sqv = ip[((long)n * VV + v) * VV + v];
    const float sqw = ip[((long)n * VV + w) * VV + w];
    const float e   = ip[base + w];

    float d2   = sqv + sqw - 2.f * e;
    float dist = sqrtf(fmaxf(d2, 1e-12f));
    float sim  = 2.f / (expf(dist) + 1.f);
    float av   = adj[base + w];
    if (w == v) { sim = 0.f; av = 0.f; }

    float s1 = warpSum(fabsf(sim));
    float s2 = warpSum(fabsf(av));
    if ((w & 31) == 0) { reda[w >> 5] = s1; redb[w >> 5] = s2; }
    __syncthreads();
    const float ssum = reda[0] + reda[1] + reda[2] + reda[3];
    const float asum = redb[0] + redb[1] + redb[2] + redb[3];

    graph[base + w] = 0.5f * (av / fmaxf(asum, 1e-12f) + sim / fmaxf(ssum, 1e-12f));
}

// ------------------------- batch-norm stats --------------------------------
__global__ void bn_stats(const float* __restrict__ hp,
                         float* __restrict__ mean, float* __restrict__ var,
                         int rows, int C)
{
    __shared__ float shs[8][32];
    __shared__ float shs2[8][32];
    const int lane = threadIdx.x & 31;
    const int ry   = threadIdx.x >> 5;
    const int c    = blockIdx.x * 32 + lane;

    float s = 0.f, s2 = 0.f;
    for (int r = ry; r < rows; r += 8) {
        float v = hp[(long)r * C + c];
        s += v; s2 += v * v;
    }
    shs[ry][lane] = s; shs2[ry][lane] = s2;
    __syncthreads();
    if (ry == 0) {
#pragma unroll
        for (int j = 1; j < 8; j++) { s += shs[j][lane]; s2 += shs2[j][lane]; }
        float mu = s / rows;
        mean[c] = mu;
        var[c]  = s2 / rows - mu * mu;
    }
}

// ------------------- BN apply + LeakyReLU + residual -----------------------
__global__ void bn_apply(const float* __restrict__ inp,
                         const float* __restrict__ hp,
                         const float* __restrict__ mean,
                         const float* __restrict__ var,
                         const float* __restrict__ bw,
                         const float* __restrict__ bb,
                         const float* __restrict__ gptr,
                         float* __restrict__ out, int total, int C)
{
    const int idx = blockIdx.x * blockDim.x + threadIdx.x;
    if (idx >= total) return;
    const int c = idx & (C - 1);
    const float g = *gptr;
    float vv = (hp[idx] - mean[c]) * rsqrtf(var[c] + 1e-5f) * bw[c] + bb[c];
    float lr = vv > 0.f ? vv : 0.1f * vv;
    out[idx] = inp[idx] + g * lr;
}

// ------------------------------ host side ----------------------------------
static void launch_gemm(int TA, int TB,
                        const float* A, const float* B, float* C,
                        int M, int N, int K,
                        long sA, long sB, long sC, int batch,
                        const float* bias,
                        const float* Res, long sRes,
                        float aH, const float* aD, cudaStream_t st)
{
    dim3 grid(N / 128, M / 128, batch);
    dim3 blk(256);
    if (TA == 0 && TB == 0)
        gemm_kernel<0, 0><<<grid, blk, 0, st>>>(A, B, C, M, N, K, sA, sB, sC, bias, Res, sRes, aH, aD);
    else if (TA == 1 && TB == 0)
        gemm_kernel<1, 0><<<grid, blk, 0, st>>>(A, B, C, M, N, K, sA, sB, sC, bias, Res, sRes, aH, aD);
    else
        gemm_kernel<0, 1><<<grid, blk, 0, st>>>(A, B, C, M, N, K, sA, sB, sC, bias, Res, sRes, aH, aD);
}

extern "C" void kernel_launch(void* const* d_in, const int* in_sizes, int n_in,
                              void* d_out, int out_size)
{
    const float* x     = (const float*)d_in[0];
    const float* vfeat = (const float*)d_in[1];
    const float* adj   = (const float*)d_in[2];
    const float* Wq    = (const float*)d_in[3];
    const float* bq    = (const float*)d_in[4];
    const float* Wk    = (const float*)d_in[5];
    const float* bk    = (const float*)d_in[6];
    const float* Wv    = (const float*)d_in[7];
    const float* bv    = (const float*)d_in[8];
    const float* gpam  = (const float*)d_in[9];
    const float* gcam  = (const float*)d_in[10];
    const float* Wg    = (const float*)d_in[11];
    const float* bnw   = (const float*)d_in[12];
    const float* bnb   = (const float*)d_in[13];
    const float* gg    = (const float*)d_in[14];
    float* out = (float*)d_out;

    float *q, *k, *v, *att1, *y1, *h, *ip, *graph, *hp, *gbuf, *mean, *var;
    cudaGetSymbolAddress((void**)&q,    d_q);
    cudaGetSymbolAddress((void**)&k,    d_k);
    cudaGetSymbolAddress((void**)&v,    d_v);
    cudaGetSymbolAddress((void**)&att1, d_att1);
    cudaGetSymbolAddress((void**)&y1,   d_y1);
    cudaGetSymbolAddress((void**)&h,    d_h);
    cudaGetSymbolAddress((void**)&ip,   d_ip);
    cudaGetSymbolAddress((void**)&graph,d_graph);
    cudaGetSymbolAddress((void**)&hp,   d_hp);
    cudaGetSymbolAddress((void**)&gbuf, d_gbuf);
    cudaGetSymbolAddress((void**)&mean, d_mean);
    cudaGetSymbolAddress((void**)&var,  d_var);

    static int smem_set = 0;
    if (!smem_set) {
        cudaFuncSetAttribute(cam_fused_kernel,
                             cudaFuncAttributeMaxDynamicSharedMemorySize, CAM_SMEM);
        smem_set = 1;
    }
    // fork/join stream + events: created once on the first (uncaptured) call.
    static cudaStream_t s2 = [](){ cudaStream_t s;
        cudaStreamCreateWithFlags(&s, cudaStreamNonBlocking); return s; }();
    static cudaEvent_t evF = [](){ cudaEvent_t e;
        cudaEventCreateWithFlags(&e, cudaEventDisableTiming); return e; }();
    static cudaEvent_t evJ = [](){ cudaEvent_t e;
        cudaEventCreateWithFlags(&e, cudaEventDisableTiming); return e; }();

    const long CHW = (long)CCH * HW;          // 262144
    const long QHW = (long)C8 * HW;           // 32768
    const long GST = (long)VV * CCH;          // 262144
    cudaStream_t s0 = 0;

    // ---- fork: graph chain runs on s2, PAM+CAM on default stream ----
    cudaEventRecord(evF, s0);
    cudaStreamWaitEvent(s2, evF, 0);

    // ---------------- PAM (s0) ----------------
    launch_gemm(0, 0, Wq, x, q, C8,  HW, CCH, 0, CHW, QHW, BSZ, bq, nullptr, 0, 1.f, nullptr, s0);
    launch_gemm(0, 0, Wk, x, k, C8,  HW, CCH, 0, CHW, QHW, BSZ, bk, nullptr, 0, 1.f, nullptr, s0);
    launch_gemm(0, 0, Wv, x, v, CCH, HW, CCH, 0, CHW, CHW, BSZ, bv, nullptr, 0, 1.f, nullptr, s0);
    launch_gemm(1, 0, q, k, att1, HW, HW, C8, QHW, QHW, (long)HW * HW, BSZ,
                nullptr, nullptr, 0, 1.f, nullptr, s0);
    softmax_kernel<<<BSZ * HW, 128, 0, s0>>>(att1, HW);
    launch_gemm(0, 1, v, att1, y1, CCH, HW, HW, CHW, (long)HW * HW, CHW, BSZ,
                nullptr, x, CHW, 0.f, gpam, s0);

    // ---------------- CAM (s0, fused flash-style) ----------------
    {
        dim3 grid(CCH / CAM_BR, BSZ);
        cam_fused_kernel<<<grid, 256, CAM_SMEM, s0>>>(y1, gcam, out);
    }

    // ------------- Graph layers (s2) -------------
    const float* inp = vfeat;
    for (int i = 0; i < GNUM; i++) {
        float* outg = (i == GNUM - 1) ? (out + (long)BSZ * CCH * HW) : gbuf;
        launch_gemm(0, 1, inp, Wg + (long)i * CCH * CCH, h,
                    NV * VV, CCH, CCH, 0, 0, 0, 1, nullptr, nullptr, 0, 1.f, nullptr, s2);
        launch_gemm(0, 1, inp, inp, ip, VV, VV, CCH, GST, GST, (long)VV * VV, NV,
                    nullptr, nullptr, 0, 1.f, nullptr, s2);
        graph_build<<<dim3(VV, NV), VV, 0, s2>>>(ip, adj, graph);
        launch_gemm(0, 0, graph, h, hp, VV, CCH, VV, (long)VV * VV, GST, GST, NV,
                    nullptr, nullptr, 0, 1.f, nullptr, s2);
        bn_stats<<<CCH / 32, 256, 0, s2>>>(hp, mean, var, NV * VV, CCH);
        bn_apply<<<(NV * VV * CCH + 255) / 256, 256, 0, s2>>>(
            inp, hp, mean, var, bnw + (long)i * CCH, bnb + (long)i * CCH,
            gg + i, outg, NV * VV * CCH, CCH);
        inp = outg;
    }

    // ---- join ----
    cudaEventRecord(evJ, s2);
    cudaStreamWaitEvent(s0, evJ, 0);
}

// round 5
// speedup vs baseline: 1.8288x; 1.2843x over previous
#include <cuda_runtime.h>
#include <cuda_bf16.h>
#include <math.h>

// ---------------------------------------------------------------------------
// Problem constants
// ---------------------------------------------------------------------------
#define BSZ   16
#define CCH   2048
#define HW    128
#define C8    256
#define NV    16
#define VV    128
#define GNUM  2

// ------------------------- scratch (device globals) ------------------------
__device__ __align__(256) float d_q   [BSZ * C8 * HW];
__device__ __align__(256) float d_k   [BSZ * C8 * HW];
__device__ __align__(256) float d_v   [BSZ * CCH * HW];
__device__ __align__(256) float d_att1[BSZ * HW * HW];
__device__ __align__(256) float d_y1  [BSZ * CCH * HW];
__device__ __align__(256) float d_h   [NV * VV * CCH];
__device__ __align__(256) float d_ip  [NV * VV * VV];
__device__ __align__(256) float d_graph[NV * VV * VV];
__device__ __align__(256) float d_hp  [NV * VV * CCH];
__device__ __align__(256) float d_gbuf[NV * VV * CCH];
__device__ __align__(256) float d_mean[CCH];
__device__ __align__(256) float d_var [CCH];

// ======================= bf16-split tensor-core GEMM ========================
// C[b] = alpha * op(A[b]) @ op(B[b]) + bias[m] + Res[b]
// A decomposed hi+lo bf16; acc = AhBh + AhBl + AlBh (fp32 accum, mma.sync).
// Block tile 128x128, K-step 32, 256 threads (8 warps, each 32x64).
// TA==0: A MxK row-major; TA==1: A KxM row-major.
// TB==0: B KxN row-major; TB==1: B NxK row-major.
#define TST   40                    // bf16 row stride (32 + 8 pad)
#define TTILE (128 * TST)           // bf16 elems per part tile
#define TSMEM (2 * 4 * TTILE * 2)   // bytes: 2 bufs x {Ah,Al,Bh,Bl}

__device__ __forceinline__ void ldsm4(unsigned* r, unsigned addr) {
    asm volatile("ldmatrix.sync.aligned.m8n8.x4.shared.b16 {%0,%1,%2,%3}, [%4];"
        : "=r"(r[0]), "=r"(r[1]), "=r"(r[2]), "=r"(r[3]) : "r"(addr));
}
__device__ __forceinline__ void mma16816(float* c, const unsigned* a, const unsigned* b) {
    asm volatile("mma.sync.aligned.m16n8k16.row.col.f32.bf16.bf16.f32 "
        "{%0,%1,%2,%3}, {%4,%5,%6,%7}, {%8,%9}, {%0,%1,%2,%3};"
        : "+f"(c[0]), "+f"(c[1]), "+f"(c[2]), "+f"(c[3])
        : "r"(a[0]), "r"(a[1]), "r"(a[2]), "r"(a[3]), "r"(b[0]), "r"(b[1]));
}
__device__ __forceinline__ void bsplit(float x, __nv_bfloat16& h, __nv_bfloat16& l) {
    h = __float2bfloat16(x);
    l = __float2bfloat16(x - __bfloat162float(h));
}

template<int TA, int TB>
__global__ __launch_bounds__(256)
void tgemm_kernel(const float* __restrict__ Ag, const float* __restrict__ Bg,
                  float* __restrict__ Cg,
                  int M, int N, int K,
                  long sA, long sB, long sC,
                  const float* __restrict__ bias,
                  const float* __restrict__ Res, long sRes,
                  float alphaH, const float* __restrict__ alphaD)
{
    extern __shared__ __align__(16) __nv_bfloat16 ts[];

    const int bz = blockIdx.z;
    const float* A = Ag + (long)bz * sA;
    const float* B = Bg + (long)bz * sB;
    float*       C = Cg + (long)bz * sC;

    const int m0 = blockIdx.y * 128;
    const int n0 = blockIdx.x * 128;
    const int tid  = threadIdx.x;
    const int wid  = tid >> 5;
    const int lane = tid & 31;
    const int warp_m = (wid >> 1) * 32;
    const int warp_n = (wid & 1) * 64;
    const int mi = lane >> 3, ri = lane & 7;
    const int g  = lane >> 2, t  = lane & 3;

    const unsigned sbase = (unsigned)__cvta_generic_to_shared(ts);

    // per-lane ldmatrix byte offsets within a part tile
    unsigned aoff[2], boff[4];
#pragma unroll
    for (int fi = 0; fi < 2; fi++)
        aoff[fi] = ((warp_m + fi * 16 + ((mi & 1) << 3) + ri) * TST + ((mi >> 1) << 3)) * 2;
#pragma unroll
    for (int fp = 0; fp < 4; fp++)
        boff[fp] = ((warp_n + fp * 16 + ((mi >> 1) << 3) + ri) * TST + ((mi & 1) << 3)) * 2;

    float acc[2][8][4];
#pragma unroll
    for (int i = 0; i < 2; i++)
#pragma unroll
        for (int j = 0; j < 8; j++)
#pragma unroll
            for (int q = 0; q < 4; q++) acc[i][j][q] = 0.f;

    // global prefetch registers
    float4 pa[4], pb[4];

    // load-index precompute
    const int rA = tid >> 1, cA = (tid & 1) * 16;     // direct path (row-major M/N x K)
    const int kA = tid >> 3, mA = (tid & 7) * 16;     // transpose path (K x M/N)

#define LOADG(k0)                                                              \
    do {                                                                       \
        if (TA == 0) {                                                         \
            _Pragma("unroll")                                                  \
            for (int j = 0; j < 4; j++)                                        \
                pa[j] = *(const float4*)&A[(long)(m0 + rA) * K + (k0) + cA + 4 * j]; \
        } else {                                                               \
            _Pragma("unroll")                                                  \
            for (int j = 0; j < 4; j++)                                        \
                pa[j] = *(const float4*)&A[(long)((k0) + kA) * M + m0 + mA + 4 * j]; \
        }                                                                      \
        if (TB == 1) {                                                         \
            _Pragma("unroll")                                                  \
            for (int j = 0; j < 4; j++)                                        \
                pb[j] = *(const float4*)&B[(long)(n0 + rA) * K + (k0) + cA + 4 * j]; \
        } else {                                                               \
            _Pragma("unroll")                                                  \
            for (int j = 0; j < 4; j++)                                        \
                pb[j] = *(const float4*)&B[(long)((k0) + kA) * N + n0 + mA + 4 * j]; \
        }                                                                      \
    } while (0)

#define CVSTORE(bf)                                                            \
    do {                                                                       \
        __nv_bfloat16* Ah = ts + ((bf) * 4 + 0) * TTILE;                       \
        __nv_bfloat16* Al = ts + ((bf) * 4 + 1) * TTILE;                       \
        __nv_bfloat16* Bh = ts + ((bf) * 4 + 2) * TTILE;                       \
        __nv_bfloat16* Bl = ts + ((bf) * 4 + 3) * TTILE;                       \
        _Pragma("unroll")                                                      \
        for (int j = 0; j < 4; j++) {                                          \
            float v[4] = { pa[j].x, pa[j].y, pa[j].z, pa[j].w };               \
            __nv_bfloat16 h[4], l[4];                                          \
            _Pragma("unroll")                                                  \
            for (int i = 0; i < 4; i++) bsplit(v[i], h[i], l[i]);              \
            if (TA == 0) {                                                     \
                int base = rA * TST + cA + 4 * j;                              \
                __nv_bfloat162 h01; h01.x = h[0]; h01.y = h[1];                \
                __nv_bfloat162 h23; h23.x = h[2]; h23.y = h[3];                \
                __nv_bfloat162 l01; l01.x = l[0]; l01.y = l[1];                \
                __nv_bfloat162 l23; l23.x = l[2]; l23.y = l[3];                \
                *(__nv_bfloat162*)(Ah + base)     = h01;                       \
                *(__nv_bfloat162*)(Ah + base + 2) = h23;                       \
                *(__nv_bfloat162*)(Al + base)     = l01;                       \
                *(__nv_bfloat162*)(Al + base + 2) = l23;                       \
            } else {                                                           \
                _Pragma("unroll")                                              \
                for (int i = 0; i < 4; i++) {                                  \
                    int row = mA + 4 * j + i;                                  \
                    Ah[row * TST + kA] = h[i];                                 \
                    Al[row * TST + kA] = l[i];                                 \
                }                                                              \
            }                                                                  \
        }                                                                      \
        _Pragma("unroll")                                                      \
        for (int j = 0; j < 4; j++) {                                          \
            float v[4] = { pb[j].x, pb[j].y, pb[j].z, pb[j].w };               \
            __nv_bfloat16 h[4], l[4];                                          \
            _Pragma("unroll")                                                  \
            for (int i = 0; i < 4; i++) bsplit(v[i], h[i], l[i]);              \
            if (TB == 1) {                                                     \
                int base = rA * TST + cA + 4 * j;                              \
                __nv_bfloat162 h01; h01.x = h[0]; h01.y = h[1];                \
                __nv_bfloat162 h23; h23.x = h[2]; h23.y = h[3];                \
                __nv_bfloat162 l01; l01.x = l[0]; l01.y = l[1];                \
                __nv_bfloat162 l23; l23.x = l[2]; l23.y = l[3];                \
                *(__nv_bfloat162*)(Bh + base)     = h01;                       \
                *(__nv_bfloat162*)(Bh + base + 2) = h23;                       \
                *(__nv_bfloat162*)(Bl + base)     = l01;                       \
                *(__nv_bfloat162*)(Bl + base + 2) = l23;                       \
            } else {                                                           \
                _Pragma("unroll")                                              \
                for (int i = 0; i < 4; i++) {                                  \
                    int row = mA + 4 * j + i;                                  \
                    Bh[row * TST + kA] = h[i];                                 \
                    Bl[row * TST + kA] = l[i];                                 \
                }                                                              \
            }                                                                  \
        }                                                                      \
    } while (0)

#define MMASTEP(bf)                                                            \
    do {                                                                       \
        const unsigned bAh = sbase + ((bf) * 4 + 0) * TTILE * 2;               \
        const unsigned bAl = sbase + ((bf) * 4 + 1) * TTILE * 2;               \
        const unsigned bBh = sbase + ((bf) * 4 + 2) * TTILE * 2;               \
        const unsigned bBl = sbase + ((bf) * 4 + 3) * TTILE * 2;               \
        _Pragma("unroll")                                                      \
        for (int kk = 0; kk < 2; kk++) {                                       \
            unsigned ah[2][4], al[2][4], bh[4][4], bl[4][4];                   \
            _Pragma("unroll")                                                  \
            for (int fi = 0; fi < 2; fi++) {                                   \
                ldsm4(ah[fi], bAh + aoff[fi] + kk * 32);                       \
                ldsm4(al[fi], bAl + aoff[fi] + kk * 32);                       \
            }                                                                  \
            _Pragma("unroll")                                                  \
            for (int fp = 0; fp < 4; fp++) {                                   \
                ldsm4(bh[fp], bBh + boff[fp] + kk * 32);                       \
                ldsm4(bl[fp], bBl + boff[fp] + kk * 32);                       \
            }                                                                  \
            _Pragma("unroll")                                                  \
            for (int fi = 0; fi < 2; fi++)                                     \
                _Pragma("unroll")                                              \
                for (int fp = 0; fp < 4; fp++)                                 \
                    _Pragma("unroll")                                          \
                    for (int hh = 0; hh < 2; hh++) {                           \
                        float* c = acc[fi][fp * 2 + hh];                       \
                        mma16816(c, ah[fi], &bh[fp][2 * hh]);                  \
                        mma16816(c, ah[fi], &bl[fp][2 * hh]);                  \
                        mma16816(c, al[fi], &bh[fp][2 * hh]);                  \
                    }                                                          \
        }                                                                      \
    } while (0)

    LOADG(0);
    CVSTORE(0);
    __syncthreads();

    const int nt = K / 32;
    for (int tI = 0; tI < nt; tI++) {
        if (tI + 1 < nt) LOADG((tI + 1) * 32);
        MMASTEP(tI & 1);
        if (tI + 1 < nt) {
            CVSTORE((tI + 1) & 1);
            __syncthreads();
        }
    }

    // ------------------------------ epilogue -------------------------------
    const float alpha = alphaD ? *alphaD : alphaH;
#pragma unroll
    for (int fi = 0; fi < 2; fi++) {
        const int m = m0 + warp_m + fi * 16 + g;
        const float bi0 = bias ? __ldg(&bias[m])     : 0.f;
        const float bi1 = bias ? __ldg(&bias[m + 8]) : 0.f;
#pragma unroll
        for (int fj = 0; fj < 8; fj++) {
            const int n = n0 + warp_n + fj * 8 + t * 2;
            const float* c = acc[fi][fj];
            const long off0 = (long)m * N + n;
            const long off1 = (long)(m + 8) * N + n;
            float2 o0, o1;
            o0.x = alpha * c[0] + bi0; o0.y = alpha * c[1] + bi0;
            o1.x = alpha * c[2] + bi1; o1.y = alpha * c[3] + bi1;
            if (Res) {
                float2 r0 = *(const float2*)&Res[(long)bz * sRes + off0];
                float2 r1 = *(const float2*)&Res[(long)bz * sRes + off1];
                o0.x += r0.x; o0.y += r0.y;
                o1.x += r1.x; o1.y += r1.y;
            }
            *(float2*)&C[off0] = o0;
            *(float2*)&C[off1] = o1;
        }
    }
#undef LOADG
#undef CVSTORE
#undef MMASTEP
}

// --------------------------- reductions ------------------------------------
__device__ __forceinline__ float warpMax(float v) {
#pragma unroll
    for (int o = 16; o; o >>= 1) v = fmaxf(v, __shfl_xor_sync(0xffffffffu, v, o));
    return v;
}
__device__ __forceinline__ float warpSum(float v) {
#pragma unroll
    for (int o = 16; o; o >>= 1) v += __shfl_xor_sync(0xffffffffu, v, o);
    return v;
}
__device__ __forceinline__ float red16max(float v) {
#pragma unroll
    for (int o = 8; o; o >>= 1) v = fmaxf(v, __shfl_xor_sync(0xffffffffu, v, o));
    return v;
}
__device__ __forceinline__ float red16sum(float v) {
#pragma unroll
    for (int o = 8; o; o >>= 1) v += __shfl_xor_sync(0xffffffffu, v, o);
    return v;
}

// in-place row softmax; one block per row
__global__ void softmax_kernel(float* __restrict__ d, int ncols)
{
    __shared__ float red[32];
    __shared__ float bcast;
    const long row = blockIdx.x;
    float* p = d + row * (long)ncols;
    const int tid = threadIdx.x, nt = blockDim.x;

    float m = -1e30f;
    for (int i = tid; i < ncols; i += nt) m = fmaxf(m, p[i]);
    m = warpMax(m);
    if ((tid & 31) == 0) red[tid >> 5] = m;
    __syncthreads();
    if (tid < 32) {
        float v = (tid < (nt >> 5)) ? red[tid] : -1e30f;
        v = warpMax(v);
        if (tid == 0) bcast = v;
    }
    __syncthreads();
    m = bcast;

    float s = 0.f;
    for (int i = tid; i < ncols; i += nt) {
        float e = __expf(p[i] - m);
        p[i] = e;
        s += e;
    }
    __syncthreads();
    s = warpSum(s);
    if ((tid & 31) == 0) red[tid >> 5] = s;
    __syncthreads();
    if (tid < 32) {
        float v = (tid < (nt >> 5)) ? red[tid] : 0.f;
        v = warpSum(v);
        if (tid == 0) bcast = v;
    }
    __syncthreads();
    const float inv = 1.f / bcast;
    for (int i = tid; i < ncols; i += nt) p[i] *= inv;
}

// --------------------- fused CAM (flash-attention style) -------------------
#define CAM_BR   64
#define CAM_BC   128
#define CAM_QP   68
#define CAM_KTP  132
#define CAM_KSP  128
#define CAM_PP   68
#define CAM_SMEM ((128*CAM_QP + 128*CAM_KTP + 128*CAM_KSP + 128*CAM_PP) * 4)

__global__ __launch_bounds__(256)
void cam_fused_kernel(const float* __restrict__ y1g,
                      const float* __restrict__ gptr,
                      float* __restrict__ outg)
{
    extern __shared__ float sm[];
    float* Qst = sm;                       // [m][r]
    float* Kts = Qst + 128 * CAM_QP;       // [m][d]
    float* Ks  = Kts + 128 * CAM_KTP;      // [d][m]
    float* Pt  = Ks  + 128 * CAM_KSP;      // [d][r]

    const int b  = blockIdx.y;
    const int c0 = blockIdx.x * CAM_BR;
    const float* Y = y1g + (long)b * CCH * HW;

    const int tid = threadIdx.x;
    const int tr  = tid >> 4;
    const int tc  = tid & 15;

    for (int i = tid; i < CAM_BR * 128; i += 256) {
        int r = i >> 7, m = i & 127;
        Qst[m * CAM_QP + r] = Y[(long)(c0 + r) * HW + m];
    }

    float acc[4][8];
    float mrow[4], lrow[4];
#pragma unroll
    for (int i = 0; i < 4; i++) {
        mrow[i] = -1e30f; lrow[i] = 0.f;
#pragma unroll
        for (int j = 0; j < 8; j++) acc[i][j] = 0.f;
    }

    for (int t = 0; t < CCH / CAM_BC; t++) {
        const int d0 = t * CAM_BC;
        __syncthreads();
        for (int i = tid; i < CAM_BC * 128; i += 256) {
            int d = i >> 7, m = i & 127;
            float v = Y[(long)(d0 + d) * HW + m];
            Ks [d * CAM_KSP + m] = v;
            Kts[m * CAM_KTP + d] = v;
        }
        __syncthreads();

        float s[4][8];
#pragma unroll
        for (int i = 0; i < 4; i++)
#pragma unroll
            for (int j = 0; j < 8; j++) s[i][j] = 0.f;

#pragma unroll 4
        for (int kk = 0; kk < 128; kk++) {
            float a[4], bb[8];
            *(float4*)&a[0]  = *(const float4*)&Qst[kk * CAM_QP + tr * 4];
            *(float4*)&bb[0] = *(const float4*)&Kts[kk * CAM_KTP + tc * 4];
            *(float4*)&bb[4] = *(const float4*)&Kts[kk * CAM_KTP + 64 + tc * 4];
#pragma unroll
            for (int i = 0; i < 4; i++)
#pragma unroll
                for (int j = 0; j < 8; j++)
                    s[i][j] += a[i] * bb[j];
        }

#pragma unroll
        for (int rr = 0; rr < 4; rr++) {
            float mx = -1e30f;
#pragma unroll
            for (int j = 0; j < 8; j++) mx = fmaxf(mx, -s[rr][j]);
            mx = red16max(mx);
            float mnew  = fmaxf(mrow[rr], mx);
            float scale = __expf(mrow[rr] - mnew);
            float rs = 0.f;
#pragma unroll
            for (int j = 0; j < 8; j++) {
                float p = __expf(-s[rr][j] - mnew);
                s[rr][j] = p;
                rs += p;
            }
            rs = red16sum(rs);
            lrow[rr] = lrow[rr] * scale + rs;
            mrow[rr] = mnew;
#pragma unroll
            for (int j = 0; j < 8; j++) acc[rr][j] *= scale;
        }

#pragma unroll
        for (int rr = 0; rr < 4; rr++) {
#pragma unroll
            for (int j = 0; j < 8; j++) {
                int dl = (j < 4) ? (tc * 4 + j) : (64 + tc * 4 + (j - 4));
                Pt[dl * CAM_PP + tr * 4 + rr] = s[rr][j];
            }
        }
        __syncthreads();

#pragma unroll 4
        for (int kk = 0; kk < 128; kk++) {
            float a[4], bb[8];
            *(float4*)&a[0]  = *(const float4*)&Pt[kk * CAM_PP + tr * 4];
            *(float4*)&bb[0] = *(const float4*)&Ks[kk * CAM_KSP + tc * 4];
            *(float4*)&bb[4] = *(const float4*)&Ks[kk * CAM_KSP + 64 + tc * 4];
#pragma unroll
            for (int i = 0; i < 4; i++)
#pragma unroll
                for (int j = 0; j < 8; j++)
                    acc[i][j] += a[i] * bb[j];
        }
    }

    const float g = *gptr;
    float* O = outg + (long)b * CCH * HW;
#pragma unroll
    for (int rr = 0; rr < 4; rr++) {
        const int r = tr * 4 + rr;
        const float inv = g / lrow[rr];
#pragma unroll
        for (int jg = 0; jg < 2; jg++) {
            const int n = jg * 64 + tc * 4;
            const long off = (long)(c0 + r) * HW + n;
            float4 yv = *(const float4*)&Y[off];
            float4 o;
            o.x = acc[rr][jg * 4 + 0] * inv + yv.x;
            o.y = acc[rr][jg * 4 + 1] * inv + yv.y;
            o.z = acc[rr][jg * 4 + 2] * inv + yv.z;
            o.w = acc[rr][jg * 4 + 3] * inv + yv.w;
            *(float4*)&O[off] = o;
        }
    }
}

// ------------------------ graph construction -------------------------------
__global__ void graph_build(const float* __restrict__ ip,
                            const float* __restrict__ adj,
                            float* __restrict__ graph)
{
    __shared__ float reda[4], redb[4];
    const int n = blockIdx.y, v = blockIdx.x, w = threadIdx.x;
    const long base = ((long)n * VV + v) * VV;

    const float sqv = ip[((long)n * VV + v) * VV + v];
    const float sqw = ip[((long)n * VV + w) * VV + w];
    const float e   = ip[base + w];

    float d2   = sqv + sqw - 2.f * e;
    float dist = sqrtf(fmaxf(d2, 1e-12f));
    float sim  = 2.f / (expf(dist) + 1.f);
    float av   = adj[base + w];
    if (w == v) { sim = 0.f; av = 0.f; }

    float s1 = warpSum(fabsf(sim));
    float s2 = warpSum(fabsf(av));
    if ((w & 31) == 0) { reda[w >> 5] = s1; redb[w >> 5] = s2; }
    __syncthreads();
    const float ssum = reda[0] + reda[1] + reda[2] + reda[3];
    const float asum = redb[0] + redb[1] + redb[2] + redb[3];

    graph[base + w] = 0.5f * (av / fmaxf(asum, 1e-12f) + sim / fmaxf(ssum, 1e-12f));
}

// ------------------------- batch-norm stats --------------------------------
__global__ void bn_stats(const float* __restrict__ hp,
                         float* __restrict__ mean, float* __restrict__ var,
                         int rows, int C)
{
    __shared__ float shs[8][32];
    __shared__ float shs2[8][32];
    const int lane = threadIdx.x & 31;
    const int ry   = threadIdx.x >> 5;
    const int c    = blockIdx.x * 32 + lane;

    float s = 0.f, s2 = 0.f;
    for (int r = ry; r < rows; r += 8) {
        float v = hp[(long)r * C + c];
        s += v; s2 += v * v;
    }
    shs[ry][lane] = s; shs2[ry][lane] = s2;
    __syncthreads();
    if (ry == 0) {
#pragma unroll
        for (int j = 1; j < 8; j++) { s += shs[j][lane]; s2 += shs2[j][lane]; }
        float mu = s / rows;
        mean[c] = mu;
        var[c]  = s2 / rows - mu * mu;
    }
}

// ------------------- BN apply + LeakyReLU + residual -----------------------
__global__ void bn_apply(const float* __restrict__ inp,
                         const float* __restrict__ hp,
                         const float* __restrict__ mean,
                         const float* __restrict__ var,
                         const float* __restrict__ bw,
                         const float* __restrict__ bb,
                         const float* __restrict__ gptr,
                         float* __restrict__ out, int total, int C)
{
    const int idx = blockIdx.x * blockDim.x + threadIdx.x;
    if (idx >= total) return;
    const int c = idx & (C - 1);
    const float g = *gptr;
    float vv = (hp[idx] - mean[c]) * rsqrtf(var[c] + 1e-5f) * bw[c] + bb[c];
    float lr = vv > 0.f ? vv : 0.1f * vv;
    out[idx] = inp[idx] + g * lr;
}

// ------------------------------ host side ----------------------------------
static void launch_gemm(int TA, int TB,
                        const float* A, const float* B, float* C,
                        int M, int N, int K,
                        long sA, long sB, long sC, int batch,
                        const float* bias,
                        const float* Res, long sRes,
                        float aH, const float* aD, cudaStream_t st)
{
    dim3 grid(N / 128, M / 128, batch);
    dim3 blk(256);
    if (TA == 0 && TB == 0)
        tgemm_kernel<0, 0><<<grid, blk, TSMEM, st>>>(A, B, C, M, N, K, sA, sB, sC, bias, Res, sRes, aH, aD);
    else if (TA == 1 && TB == 0)
        tgemm_kernel<1, 0><<<grid, blk, TSMEM, st>>>(A, B, C, M, N, K, sA, sB, sC, bias, Res, sRes, aH, aD);
    else
        tgemm_kernel<0, 1><<<grid, blk, TSMEM, st>>>(A, B, C, M, N, K, sA, sB, sC, bias, Res, sRes, aH, aD);
}

extern "C" void kernel_launch(void* const* d_in, const int* in_sizes, int n_in,
                              void* d_out, int out_size)
{
    const float* x     = (const float*)d_in[0];
    const float* vfeat = (const float*)d_in[1];
    const float* adj   = (const float*)d_in[2];
    const float* Wq    = (const float*)d_in[3];
    const float* bq    = (const float*)d_in[4];
    const float* Wk    = (const float*)d_in[5];
    const float* bk    = (const float*)d_in[6];
    const float* Wv    = (const float*)d_in[7];
    const float* bv    = (const float*)d_in[8];
    const float* gpam  = (const float*)d_in[9];
    const float* gcam  = (const float*)d_in[10];
    const float* Wg    = (const float*)d_in[11];
    const float* bnw   = (const float*)d_in[12];
    const float* bnb   = (const float*)d_in[13];
    const float* gg    = (const float*)d_in[14];
    float* out = (float*)d_out;

    float *q, *k, *v, *att1, *y1, *h, *ip, *graph, *hp, *gbuf, *mean, *var;
    cudaGetSymbolAddress((void**)&q,    d_q);
    cudaGetSymbolAddress((void**)&k,    d_k);
    cudaGetSymbolAddress((void**)&v,    d_v);
    cudaGetSymbolAddress((void**)&att1, d_att1);
    cudaGetSymbolAddress((void**)&y1,   d_y1);
    cudaGetSymbolAddress((void**)&h,    d_h);
    cudaGetSymbolAddress((void**)&ip,   d_ip);
    cudaGetSymbolAddress((void**)&graph,d_graph);
    cudaGetSymbolAddress((void**)&hp,   d_hp);
    cudaGetSymbolAddress((void**)&gbuf, d_gbuf);
    cudaGetSymbolAddress((void**)&mean, d_mean);
    cudaGetSymbolAddress((void**)&var,  d_var);

    static int inited = 0;
    if (!inited) {
        cudaFuncSetAttribute(tgemm_kernel<0, 0>,
                             cudaFuncAttributeMaxDynamicSharedMemorySize, TSMEM);
        cudaFuncSetAttribute(tgemm_kernel<1, 0>,
                             cudaFuncAttributeMaxDynamicSharedMemorySize, TSMEM);
        cudaFuncSetAttribute(tgemm_kernel<0, 1>,
                             cudaFuncAttributeMaxDynamicSharedMemorySize, TSMEM);
        cudaFuncSetAttribute(cam_fused_kernel,
                             cudaFuncAttributeMaxDynamicSharedMemorySize, CAM_SMEM);
        inited = 1;
    }
    static cudaStream_t s2 = [](){ cudaStream_t s;
        cudaStreamCreateWithFlags(&s, cudaStreamNonBlocking); return s; }();
    static cudaEvent_t evF = [](){ cudaEvent_t e;
        cudaEventCreateWithFlags(&e, cudaEventDisableTiming); return e; }();
    static cudaEvent_t evJ = [](){ cudaEvent_t e;
        cudaEventCreateWithFlags(&e, cudaEventDisableTiming); return e; }();

    const long CHW = (long)CCH * HW;          // 262144
    const long QHW = (long)C8 * HW;           // 32768
    const long GST = (long)VV * CCH;          // 262144
    cudaStream_t s0 = 0;

    // ---- fork ----
    cudaEventRecord(evF, s0);
    cudaStreamWaitEvent(s2, evF, 0);

    // ---------------- PAM (s0) ----------------
    launch_gemm(0, 0, Wq, x, q, C8,  HW, CCH, 0, CHW, QHW, BSZ, bq, nullptr, 0, 1.f, nullptr, s0);
    launch_gemm(0, 0, Wk, x, k, C8,  HW, CCH, 0, CHW, QHW, BSZ, bk, nullptr, 0, 1.f, nullptr, s0);
    launch_gemm(0, 0, Wv, x, v, CCH, HW, CCH, 0, CHW, CHW, BSZ, bv, nullptr, 0, 1.f, nullptr, s0);
    launch_gemm(1, 0, q, k, att1, HW, HW, C8, QHW, QHW, (long)HW * HW, BSZ,
                nullptr, nullptr, 0, 1.f, nullptr, s0);
    softmax_kernel<<<BSZ * HW, 128, 0, s0>>>(att1, HW);
    launch_gemm(0, 1, v, att1, y1, CCH, HW, HW, CHW, (long)HW * HW, CHW, BSZ,
                nullptr, x, CHW, 0.f, gpam, s0);

    // ---------------- CAM (s0) ----------------
    {
        dim3 grid(CCH / CAM_BR, BSZ);
        cam_fused_kernel<<<grid, 256, CAM_SMEM, s0>>>(y1, gcam, out);
    }

    // ------------- Graph layers (s2) -------------
    const float* inp = vfeat;
    for (int i = 0; i < GNUM; i++) {
        float* outg = (i == GNUM - 1) ? (out + (long)BSZ * CCH * HW) : gbuf;
        launch_gemm(0, 1, inp, Wg + (long)i * CCH * CCH, h,
                    NV * VV, CCH, CCH, 0, 0, 0, 1, nullptr, nullptr, 0, 1.f, nullptr, s2);
        launch_gemm(0, 1, inp, inp, ip, VV, VV, CCH, GST, GST, (long)VV * VV, NV,
                    nullptr, nullptr, 0, 1.f, nullptr, s2);
        graph_build<<<dim3(VV, NV), VV, 0, s2>>>(ip, adj, graph);
        launch_gemm(0, 0, graph, h, hp, VV, CCH, VV, (long)VV * VV, GST, GST, NV,
                    nullptr, nullptr, 0, 1.f, nullptr, s2);
        bn_stats<<<CCH / 32, 256, 0, s2>>>(hp, mean, var, NV * VV, CCH);
        bn_apply<<<(NV * VV * CCH + 255) / 256, 256, 0, s2>>>(
            inp, hp, mean, var, bnw + (long)i * CCH, bnb + (long)i * CCH,
            gg + i, outg, NV * VV * CCH, CCH);
        inp = outg;
    }

    // ---- join ----
    cudaEventRecord(evJ, s2);
    cudaStreamWaitEvent(s0, evJ, 0);
}

// round 6
// speedup vs baseline: 3.0309x; 1.6573x over previous
#include <cuda_runtime.h>
#include <cuda_bf16.h>
#include <math.h>

// ---------------------------------------------------------------------------
// Problem constants
// ---------------------------------------------------------------------------
#define BSZ   16
#define CCH   2048
#define HW    128
#define C8    256
#define NV    16
#define VV    128
#define GNUM  2

// ------------------------- scratch (device globals) ------------------------
__device__ __align__(256) float d_q   [BSZ * C8 * HW];
__device__ __align__(256) float d_k   [BSZ * C8 * HW];
__device__ __align__(256) float d_v   [BSZ * CCH * HW];
__device__ __align__(256) float d_att1[BSZ * HW * HW];
__device__ __align__(256) float d_y1  [BSZ * CCH * HW];
__device__ __align__(256) float d_h   [NV * VV * CCH];
__device__ __align__(256) float d_ip  [NV * VV * VV];
__device__ __align__(256) float d_graph[NV * VV * VV];
__device__ __align__(256) float d_hp  [NV * VV * CCH];
__device__ __align__(256) float d_gbuf[NV * VV * CCH];
__device__ __align__(256) float d_mean[CCH];
__device__ __align__(256) float d_var [CCH];

// ---------------------- shared mma/ldsm/split helpers -----------------------
__device__ __forceinline__ void ldsm4(unsigned* r, unsigned addr) {
    asm volatile("ldmatrix.sync.aligned.m8n8.x4.shared.b16 {%0,%1,%2,%3}, [%4];"
        : "=r"(r[0]), "=r"(r[1]), "=r"(r[2]), "=r"(r[3]) : "r"(addr));
}
__device__ __forceinline__ void ldsm4t(unsigned* r, unsigned addr) {
    asm volatile("ldmatrix.sync.aligned.m8n8.x4.trans.shared.b16 {%0,%1,%2,%3}, [%4];"
        : "=r"(r[0]), "=r"(r[1]), "=r"(r[2]), "=r"(r[3]) : "r"(addr));
}
__device__ __forceinline__ void mma16816(float* c, const unsigned* a, const unsigned* b) {
    asm volatile("mma.sync.aligned.m16n8k16.row.col.f32.bf16.bf16.f32 "
        "{%0,%1,%2,%3}, {%4,%5,%6,%7}, {%8,%9}, {%0,%1,%2,%3};"
        : "+f"(c[0]), "+f"(c[1]), "+f"(c[2]), "+f"(c[3])
        : "r"(a[0]), "r"(a[1]), "r"(a[2]), "r"(a[3]), "r"(b[0]), "r"(b[1]));
}
__device__ __forceinline__ void bsplit(float x, __nv_bfloat16& h, __nv_bfloat16& l) {
    h = __float2bfloat16(x);
    l = __float2bfloat16(x - __bfloat162float(h));
}
__device__ __forceinline__ unsigned packbf(float a, float b) {
    __nv_bfloat162 p; p.x = __float2bfloat16(a); p.y = __float2bfloat16(b);
    return *(unsigned*)&p;
}
__device__ __forceinline__ unsigned packlo(float a, float b, unsigned hipack) {
    __nv_bfloat162 h = *(__nv_bfloat162*)&hipack;
    return packbf(a - __bfloat162float(h.x), b - __bfloat162float(h.y));
}

// ======================= bf16-split tensor-core GEMM ========================
#define TST   40
#define TTILE (128 * TST)
#define TSMEM (2 * 4 * TTILE * 2)

template<int TA, int TB>
__global__ __launch_bounds__(256)
void tgemm_kernel(const float* __restrict__ Ag, const float* __restrict__ Bg,
                  float* __restrict__ Cg,
                  int M, int N, int K,
                  long sA, long sB, long sC,
                  const float* __restrict__ bias,
                  const float* __restrict__ Res, long sRes,
                  float alphaH, const float* __restrict__ alphaD)
{
    extern __shared__ __align__(16) __nv_bfloat16 ts[];

    const int bz = blockIdx.z;
    const float* A = Ag + (long)bz * sA;
    const float* B = Bg + (long)bz * sB;
    float*       C = Cg + (long)bz * sC;

    const int m0 = blockIdx.y * 128;
    const int n0 = blockIdx.x * 128;
    const int tid  = threadIdx.x;
    const int wid  = tid >> 5;
    const int lane = tid & 31;
    const int warp_m = (wid >> 1) * 32;
    const int warp_n = (wid & 1) * 64;
    const int mi = lane >> 3, ri = lane & 7;
    const int g  = lane >> 2, t  = lane & 3;

    const unsigned sbase = (unsigned)__cvta_generic_to_shared(ts);

    unsigned aoff[2], boff[4];
#pragma unroll
    for (int fi = 0; fi < 2; fi++)
        aoff[fi] = ((warp_m + fi * 16 + ((mi & 1) << 3) + ri) * TST + ((mi >> 1) << 3)) * 2;
#pragma unroll
    for (int fp = 0; fp < 4; fp++)
        boff[fp] = ((warp_n + fp * 16 + ((mi >> 1) << 3) + ri) * TST + ((mi & 1) << 3)) * 2;

    float acc[2][8][4];
#pragma unroll
    for (int i = 0; i < 2; i++)
#pragma unroll
        for (int j = 0; j < 8; j++)
#pragma unroll
            for (int q = 0; q < 4; q++) acc[i][j][q] = 0.f;

    float4 pa[4], pb[4];
    const int rA = tid >> 1, cA = (tid & 1) * 16;
    const int kA = tid >> 3, mA = (tid & 7) * 16;

#define LOADG(k0)                                                              \
    do {                                                                       \
        if (TA == 0) {                                                         \
            _Pragma("unroll")                                                  \
            for (int j = 0; j < 4; j++)                                        \
                pa[j] = *(const float4*)&A[(long)(m0 + rA) * K + (k0) + cA + 4 * j]; \
        } else {                                                               \
            _Pragma("unroll")                                                  \
            for (int j = 0; j < 4; j++)                                        \
                pa[j] = *(const float4*)&A[(long)((k0) + kA) * M + m0 + mA + 4 * j]; \
        }                                                                      \
        if (TB == 1) {                                                         \
            _Pragma("unroll")                                                  \
            for (int j = 0; j < 4; j++)                                        \
                pb[j] = *(const float4*)&B[(long)(n0 + rA) * K + (k0) + cA + 4 * j]; \
        } else {                                                               \
            _Pragma("unroll")                                                  \
            for (int j = 0; j < 4; j++)                                        \
                pb[j] = *(const float4*)&B[(long)((k0) + kA) * N + n0 + mA + 4 * j]; \
        }                                                                      \
    } while (0)

#define CVSTORE(bf)                                                            \
    do {                                                                       \
        __nv_bfloat16* Ah = ts + ((bf) * 4 + 0) * TTILE;                       \
        __nv_bfloat16* Al = ts + ((bf) * 4 + 1) * TTILE;                       \
        __nv_bfloat16* Bh = ts + ((bf) * 4 + 2) * TTILE;                       \
        __nv_bfloat16* Bl = ts + ((bf) * 4 + 3) * TTILE;                       \
        _Pragma("unroll")                                                      \
        for (int j = 0; j < 4; j++) {                                          \
            float v[4] = { pa[j].x, pa[j].y, pa[j].z, pa[j].w };               \
            __nv_bfloat16 h[4], l[4];                                          \
            _Pragma("unroll")                                                  \
            for (int i = 0; i < 4; i++) bsplit(v[i], h[i], l[i]);              \
            if (TA == 0) {                                                     \
                int base = rA * TST + cA + 4 * j;                              \
                __nv_bfloat162 h01; h01.x = h[0]; h01.y = h[1];                \
                __nv_bfloat162 h23; h23.x = h[2]; h23.y = h[3];                \
                __nv_bfloat162 l01; l01.x = l[0]; l01.y = l[1];                \
                __nv_bfloat162 l23; l23.x = l[2]; l23.y = l[3];                \
                *(__nv_bfloat162*)(Ah + base)     = h01;                       \
                *(__nv_bfloat162*)(Ah + base + 2) = h23;                       \
                *(__nv_bfloat162*)(Al + base)     = l01;                       \
                *(__nv_bfloat162*)(Al + base + 2) = l23;                       \
            } else {                                                           \
                _Pragma("unroll")                                              \
                for (int i = 0; i < 4; i++) {                                  \
                    int row = mA + 4 * j + i;                                  \
                    Ah[row * TST + kA] = h[i];                                 \
                    Al[row * TST + kA] = l[i];                                 \
                }                                                              \
            }                                                                  \
        }                                                                      \
        _Pragma("unroll")                                                      \
        for (int j = 0; j < 4; j++) {                                          \
            float v[4] = { pb[j].x, pb[j].y, pb[j].z, pb[j].w };               \
            __nv_bfloat16 h[4], l[4];                                          \
            _Pragma("unroll")                                                  \
            for (int i = 0; i < 4; i++) bsplit(v[i], h[i], l[i]);              \
            if (TB == 1) {                                                     \
                int base = rA * TST + cA + 4 * j;                              \
                __nv_bfloat162 h01; h01.x = h[0]; h01.y = h[1];                \
                __nv_bfloat162 h23; h23.x = h[2]; h23.y = h[3];                \
                __nv_bfloat162 l01; l01.x = l[0]; l01.y = l[1];                \
                __nv_bfloat162 l23; l23.x = l[2]; l23.y = l[3];                \
                *(__nv_bfloat162*)(Bh + base)     = h01;                       \
                *(__nv_bfloat162*)(Bh + base + 2) = h23;                       \
                *(__nv_bfloat162*)(Bl + base)     = l01;                       \
                *(__nv_bfloat162*)(Bl + base + 2) = l23;                       \
            } else {                                                           \
                _Pragma("unroll")                                              \
                for (int i = 0; i < 4; i++) {                                  \
                    int row = mA + 4 * j + i;                                  \
                    Bh[row * TST + kA] = h[i];                                 \
                    Bl[row * TST + kA] = l[i];                                 \
                }                                                              \
            }                                                                  \
        }                                                                      \
    } while (0)

#define MMASTEP(bf)                                                            \
    do {                                                                       \
        const unsigned bAh = sbase + ((bf) * 4 + 0) * TTILE * 2;               \
        const unsigned bAl = sbase + ((bf) * 4 + 1) * TTILE * 2;               \
        const unsigned bBh = sbase + ((bf) * 4 + 2) * TTILE * 2;               \
        const unsigned bBl = sbase + ((bf) * 4 + 3) * TTILE * 2;               \
        _Pragma("unroll")                                                      \
        for (int kk = 0; kk < 2; kk++) {                                       \
            unsigned ah[2][4], al[2][4], bh[4][4], bl[4][4];                   \
            _Pragma("unroll")                                                  \
            for (int fi = 0; fi < 2; fi++) {                                   \
                ldsm4(ah[fi], bAh + aoff[fi] + kk * 32);                       \
                ldsm4(al[fi], bAl + aoff[fi] + kk * 32);                       \
            }                                                                  \
            _Pragma("unroll")                                                  \
            for (int fp = 0; fp < 4; fp++) {                                   \
                ldsm4(bh[fp], bBh + boff[fp] + kk * 32);                       \
                ldsm4(bl[fp], bBl + boff[fp] + kk * 32);                       \
            }                                                                  \
            _Pragma("unroll")                                                  \
            for (int fi = 0; fi < 2; fi++)                                     \
                _Pragma("unroll")                                              \
                for (int fp = 0; fp < 4; fp++)                                 \
                    _Pragma("unroll")                                          \
                    for (int hh = 0; hh < 2; hh++) {                           \
                        float* c = acc[fi][fp * 2 + hh];                       \
                        mma16816(c, ah[fi], &bh[fp][2 * hh]);                  \
                        mma16816(c, ah[fi], &bl[fp][2 * hh]);                  \
                        mma16816(c, al[fi], &bh[fp][2 * hh]);                  \
                    }                                                          \
        }                                                                      \
    } while (0)

    LOADG(0);
    CVSTORE(0);
    __syncthreads();

    const int nt = K / 32;
    for (int tI = 0; tI < nt; tI++) {
        if (tI + 1 < nt) LOADG((tI + 1) * 32);
        MMASTEP(tI & 1);
        if (tI + 1 < nt) {
            CVSTORE((tI + 1) & 1);
            __syncthreads();
        }
    }

    const float alpha = alphaD ? *alphaD : alphaH;
#pragma unroll
    for (int fi = 0; fi < 2; fi++) {
        const int m = m0 + warp_m + fi * 16 + g;
        const float bi0 = bias ? __ldg(&bias[m])     : 0.f;
        const float bi1 = bias ? __ldg(&bias[m + 8]) : 0.f;
#pragma unroll
        for (int fj = 0; fj < 8; fj++) {
            const int n = n0 + warp_n + fj * 8 + t * 2;
            const float* c = acc[fi][fj];
            const long off0 = (long)m * N + n;
            const long off1 = (long)(m + 8) * N + n;
            float2 o0, o1;
            o0.x = alpha * c[0] + bi0; o0.y = alpha * c[1] + bi0;
            o1.x = alpha * c[2] + bi1; o1.y = alpha * c[3] + bi1;
            if (Res) {
                float2 r0 = *(const float2*)&Res[(long)bz * sRes + off0];
                float2 r1 = *(const float2*)&Res[(long)bz * sRes + off1];
                o0.x += r0.x; o0.y += r0.y;
                o1.x += r1.x; o1.y += r1.y;
            }
            *(float2*)&C[off0] = o0;
            *(float2*)&C[off1] = o1;
        }
    }
#undef LOADG
#undef CVSTORE
#undef MMASTEP
}

// --------------------------- reductions ------------------------------------
__device__ __forceinline__ float warpMax(float v) {
#pragma unroll
    for (int o = 16; o; o >>= 1) v = fmaxf(v, __shfl_xor_sync(0xffffffffu, v, o));
    return v;
}
__device__ __forceinline__ float warpSum(float v) {
#pragma unroll
    for (int o = 16; o; o >>= 1) v += __shfl_xor_sync(0xffffffffu, v, o);
    return v;
}

// in-place row softmax; one block per row
__global__ void softmax_kernel(float* __restrict__ d, int ncols)
{
    __shared__ float red[32];
    __shared__ float bcast;
    const long row = blockIdx.x;
    float* p = d + row * (long)ncols;
    const int tid = threadIdx.x, nt = blockDim.x;

    float m = -1e30f;
    for (int i = tid; i < ncols; i += nt) m = fmaxf(m, p[i]);
    m = warpMax(m);
    if ((tid & 31) == 0) red[tid >> 5] = m;
    __syncthreads();
    if (tid < 32) {
        float v = (tid < (nt >> 5)) ? red[tid] : -1e30f;
        v = warpMax(v);
        if (tid == 0) bcast = v;
    }
    __syncthreads();
    m = bcast;

    float s = 0.f;
    for (int i = tid; i < ncols; i += nt) {
        float e = __expf(p[i] - m);
        p[i] = e;
        s += e;
    }
    __syncthreads();
    s = warpSum(s);
    if ((tid & 31) == 0) red[tid >> 5] = s;
    __syncthreads();
    if (tid < 32) {
        float v = (tid < (nt >> 5)) ? red[tid] : 0.f;
        v = warpSum(v);
        if (tid == 0) bcast = v;
    }
    __syncthreads();
    const float inv = 1.f / bcast;
    for (int i = tid; i < ncols; i += nt) p[i] *= inv;
}

// ================= tensor-core fused CAM (flash style) ======================
// Q = K = V = rows of y1[b] (2048 x 128). scores = -(Q @ K^T).
// Block = 128 q-rows; 8 warps x 16 rows, each warp owns the full 128-col
// stripe. Smem: Qhi/Qlo/Khi/Klo [128][136] bf16 (stride 136 -> conflict-free
// ldsm). PV B-frags via ldmatrix.trans on the K tiles (no transposed copy).
#define CST   136
#define CTILE (128 * CST)
#define CAM_SMEM (4 * CTILE * 2)

__global__ __launch_bounds__(256)
void cam_tc_kernel(const float* __restrict__ y1g,
                   const float* __restrict__ gptr,
                   float* __restrict__ outg)
{
    extern __shared__ __align__(16) __nv_bfloat16 cs[];
    __nv_bfloat16* Qh = cs;
    __nv_bfloat16* Ql = cs + CTILE;
    __nv_bfloat16* Kh = cs + 2 * CTILE;
    __nv_bfloat16* Kl = cs + 3 * CTILE;

    const int b  = blockIdx.y;
    const int c0 = blockIdx.x * 128;
    const float* Y = y1g + (long)b * CCH * HW;

    const int tid = threadIdx.x, wid = tid >> 5, lane = tid & 31;
    const int mi = lane >> 3, ri = lane & 7, g = lane >> 2, t = lane & 3;

    const unsigned sb  = (unsigned)__cvta_generic_to_shared(cs);
    const unsigned bQh = sb;
    const unsigned bQl = sb + CTILE * 2;
    const unsigned bKh = sb + 2 * CTILE * 2;
    const unsigned bKl = sb + 3 * CTILE * 2;

    // A-frag lane offset in Q (rows wid*16..+15)
    const unsigned aoff = ((wid * 16 + ((mi & 1) << 3) + ri) * CST + ((mi >> 1) << 3)) * 2;
    // B-frag (non-trans) lane offset for S: smem rows = pos(n), cols = hw(k)
    const unsigned bS = ((((mi >> 1) << 3) + ri) * CST + ((mi & 1) << 3)) * 2;
    // B-frag (trans) lane offset for PV: smem rows = pos(k), cols = hw(n)
    const unsigned bT = ((((mi & 1) << 3) + ri) * CST + ((mi >> 1) << 3)) * 2;

    // ---- load Q tile (split hi/lo) ----
    for (int idx = tid; idx < 128 * 32; idx += 256) {
        int r = idx >> 5, hw = (idx & 31) * 4;
        float4 v = *(const float4*)&Y[(long)(c0 + r) * HW + hw];
        __nv_bfloat16 h0,l0,h1,l1,h2,l2,h3,l3;
        bsplit(v.x,h0,l0); bsplit(v.y,h1,l1); bsplit(v.z,h2,l2); bsplit(v.w,h3,l3);
        __nv_bfloat162 a; __nv_bfloat162 c;
        __nv_bfloat162* ph = (__nv_bfloat162*)(Qh + r * CST + hw);
        __nv_bfloat162* pl = (__nv_bfloat162*)(Ql + r * CST + hw);
        a.x = h0; a.y = h1; ph[0] = a;  a.x = h2; a.y = h3; ph[1] = a;
        c.x = l0; c.y = l1; pl[0] = c;  c.x = l2; c.y = l3; pl[1] = c;
    }

    float Sa[16][4], Oa[16][4];
    float m0r = -1e30f, m1r = -1e30f, l0r = 0.f, l1r = 0.f;
#pragma unroll
    for (int j = 0; j < 16; j++) { Oa[j][0]=Oa[j][1]=Oa[j][2]=Oa[j][3]=0.f; }

    for (int tI = 0; tI < 16; tI++) {
        __syncthreads();   // K tiles free (and Q stores ordered on tI=0)
        for (int idx = tid; idx < 128 * 32; idx += 256) {
            int d = idx >> 5, hw = (idx & 31) * 4;
            float4 v = *(const float4*)&Y[(long)(tI * 128 + d) * HW + hw];
            __nv_bfloat16 h0,l0,h1,l1,h2,l2,h3,l3;
            bsplit(v.x,h0,l0); bsplit(v.y,h1,l1); bsplit(v.z,h2,l2); bsplit(v.w,h3,l3);
            __nv_bfloat162 a; __nv_bfloat162 c;
            __nv_bfloat162* ph = (__nv_bfloat162*)(Kh + d * CST + hw);
            __nv_bfloat162* pl = (__nv_bfloat162*)(Kl + d * CST + hw);
            a.x = h0; a.y = h1; ph[0] = a;  a.x = h2; a.y = h3; ph[1] = a;
            c.x = l0; c.y = l1; pl[0] = c;  c.x = l2; c.y = l3; pl[1] = c;
        }
        __syncthreads();

        // ---- S = Q @ K^T (3-term split) ----
#pragma unroll
        for (int j = 0; j < 16; j++) { Sa[j][0]=Sa[j][1]=Sa[j][2]=Sa[j][3]=0.f; }
#pragma unroll
        for (int ks = 0; ks < 8; ks++) {
            unsigned ah[4], al[4];
            ldsm4(ah, bQh + aoff + ks * 32);
            ldsm4(al, bQl + aoff + ks * 32);
#pragma unroll
            for (int fp = 0; fp < 8; fp++) {
                unsigned bh[4], bl[4];
                ldsm4(bh, bKh + bS + fp * (16 * CST * 2) + ks * 32);
                ldsm4(bl, bKl + bS + fp * (16 * CST * 2) + ks * 32);
#pragma unroll
                for (int hh = 0; hh < 2; hh++) {
                    float* c = Sa[fp * 2 + hh];
                    mma16816(c, ah, &bh[2 * hh]);
                    mma16816(c, ah, &bl[2 * hh]);
                    mma16816(c, al, &bh[2 * hh]);
                }
            }
        }

        // ---- online softmax (scores = -S); rows g ([0],[1]) and g+8 ([2],[3])
        float mx0 = -1e30f, mx1 = -1e30f;
#pragma unroll
        for (int j = 0; j < 16; j++) {
            mx0 = fmaxf(mx0, fmaxf(-Sa[j][0], -Sa[j][1]));
            mx1 = fmaxf(mx1, fmaxf(-Sa[j][2], -Sa[j][3]));
        }
        mx0 = fmaxf(mx0, __shfl_xor_sync(0xffffffffu, mx0, 1));
        mx0 = fmaxf(mx0, __shfl_xor_sync(0xffffffffu, mx0, 2));
        mx1 = fmaxf(mx1, __shfl_xor_sync(0xffffffffu, mx1, 1));
        mx1 = fmaxf(mx1, __shfl_xor_sync(0xffffffffu, mx1, 2));
        const float mn0 = fmaxf(m0r, mx0), mn1 = fmaxf(m1r, mx1);
        const float sc0 = __expf(m0r - mn0), sc1 = __expf(m1r - mn1);
        float rs0 = 0.f, rs1 = 0.f;
#pragma unroll
        for (int j = 0; j < 16; j++) {
            float p0 = __expf(-Sa[j][0] - mn0); Sa[j][0] = p0; rs0 += p0;
            float p1 = __expf(-Sa[j][1] - mn0); Sa[j][1] = p1; rs0 += p1;
            float p2 = __expf(-Sa[j][2] - mn1); Sa[j][2] = p2; rs1 += p2;
            float p3 = __expf(-Sa[j][3] - mn1); Sa[j][3] = p3; rs1 += p3;
        }
        rs0 += __shfl_xor_sync(0xffffffffu, rs0, 1);
        rs0 += __shfl_xor_sync(0xffffffffu, rs0, 2);
        rs1 += __shfl_xor_sync(0xffffffffu, rs1, 1);
        rs1 += __shfl_xor_sync(0xffffffffu, rs1, 2);
        l0r = l0r * sc0 + rs0;  l1r = l1r * sc1 + rs1;
        m0r = mn0;  m1r = mn1;
#pragma unroll
        for (int j = 0; j < 16; j++) {
            Oa[j][0] *= sc0; Oa[j][1] *= sc0;
            Oa[j][2] *= sc1; Oa[j][3] *= sc1;
        }

        // ---- O += P @ V  (P from accumulators; V frags via ldsm.trans) ----
#pragma unroll
        for (int kp = 0; kp < 8; kp++) {
            const float* p0 = Sa[2 * kp];
            const float* p1 = Sa[2 * kp + 1];
            unsigned aPh[4], aPl[4];
            aPh[0] = packbf(p0[0], p0[1]);
            aPh[1] = packbf(p0[2], p0[3]);
            aPh[2] = packbf(p1[0], p1[1]);
            aPh[3] = packbf(p1[2], p1[3]);
            aPl[0] = packlo(p0[0], p0[1], aPh[0]);
            aPl[1] = packlo(p0[2], p0[3], aPh[1]);
            aPl[2] = packlo(p1[0], p1[1], aPh[2]);
            aPl[3] = packlo(p1[2], p1[3], aPh[3]);
#pragma unroll
            for (int fp = 0; fp < 8; fp++) {
                unsigned vh[4], vl[4];
                ldsm4t(vh, bKh + bT + kp * (16 * CST * 2) + fp * 32);
                ldsm4t(vl, bKl + bT + kp * (16 * CST * 2) + fp * 32);
#pragma unroll
                for (int hh = 0; hh < 2; hh++) {
                    float* c = Oa[fp * 2 + hh];
                    mma16816(c, aPh, &vh[2 * hh]);
                    mma16816(c, aPh, &vl[2 * hh]);
                    mma16816(c, aPl, &vh[2 * hh]);
                }
            }
        }
    }

    // ---- epilogue: out = gamma * O / l + y1 ----
    const float gam = *gptr;
    const float i0 = gam / l0r, i1 = gam / l1r;
    const int r0 = c0 + wid * 16 + g, r1 = r0 + 8;
    float* O = outg + (long)b * CCH * HW;
#pragma unroll
    for (int j = 0; j < 16; j++) {
        const int col = j * 8 + t * 2;
        const long o0 = (long)r0 * HW + col;
        const long o1 = (long)r1 * HW + col;
        float2 y0 = *(const float2*)&Y[o0];
        float2 y1v = *(const float2*)&Y[o1];
        float2 w0, w1;
        w0.x = Oa[j][0] * i0 + y0.x;  w0.y = Oa[j][1] * i0 + y0.y;
        w1.x = Oa[j][2] * i1 + y1v.x; w1.y = Oa[j][3] * i1 + y1v.y;
        *(float2*)&O[o0] = w0;
        *(float2*)&O[o1] = w1;
    }
}

// ------------------------ graph construction -------------------------------
__global__ void graph_build(const float* __restrict__ ip,
                            const float* __restrict__ adj,
                            float* __restrict__ graph)
{
    __shared__ float reda[4], redb[4];
    const int n = blockIdx.y, v = blockIdx.x, w = threadIdx.x;
    const long base = ((long)n * VV + v) * VV;

    const float sqv = ip[((long)n * VV + v) * VV + v];
    const float sqw = ip[((long)n * VV + w) * VV + w];
    const float e   = ip[base + w];

    float d2   = sqv + sqw - 2.f * e;
    float dist = sqrtf(fmaxf(d2, 1e-12f));
    float sim  = 2.f / (expf(dist) + 1.f);
    float av   = adj[base + w];
    if (w == v) { sim = 0.f; av = 0.f; }

    float s1 = warpSum(fabsf(sim));
    float s2 = warpSum(fabsf(av));
    if ((w & 31) == 0) { reda[w >> 5] = s1; redb[w >> 5] = s2; }
    __syncthreads();
    const float ssum = reda[0] + reda[1] + reda[2] + reda[3];
    const float asum = redb[0] + redb[1] + redb[2] + redb[3];

    graph[base + w] = 0.5f * (av / fmaxf(asum, 1e-12f) + sim / fmaxf(ssum, 1e-12f));
}

// ------------------------- batch-norm stats --------------------------------
__global__ void bn_stats(const float* __restrict__ hp,
                         float* __restrict__ mean, float* __restrict__ var,
                         int rows, int C)
{
    __shared__ float shs[8][32];
    __shared__ float shs2[8][32];
    const int lane = threadIdx.x & 31;
    const int ry   = threadIdx.x >> 5;
    const int c    = blockIdx.x * 32 + lane;

    float s = 0.f, s2 = 0.f;
    for (int r = ry; r < rows; r += 8) {
        float v = hp[(long)r * C + c];
        s += v; s2 += v * v;
    }
    shs[ry][lane] = s; shs2[ry][lane] = s2;
    __syncthreads();
    if (ry == 0) {
#pragma unroll
        for (int j = 1; j < 8; j++) { s += shs[j][lane]; s2 += shs2[j][lane]; }
        float mu = s / rows;
        mean[c] = mu;
        var[c]  = s2 / rows - mu * mu;
    }
}

// ------------------- BN apply + LeakyReLU + residual -----------------------
__global__ void bn_apply(const float* __restrict__ inp,
                         const float* __restrict__ hp,
                         const float* __restrict__ mean,
                         const float* __restrict__ var,
                         const float* __restrict__ bw,
                         const float* __restrict__ bb,
                         const float* __restrict__ gptr,
                         float* __restrict__ out, int total, int C)
{
    const int idx = blockIdx.x * blockDim.x + threadIdx.x;
    if (idx >= total) return;
    const int c = idx & (C - 1);
    const float g = *gptr;
    float vv = (hp[idx] - mean[c]) * rsqrtf(var[c] + 1e-5f) * bw[c] + bb[c];
    float lr = vv > 0.f ? vv : 0.1f * vv;
    out[idx] = inp[idx] + g * lr;
}

// ------------------------------ host side ----------------------------------
static void launch_gemm(int TA, int TB,
                        const float* A, const float* B, float* C,
                        int M, int N, int K,
                        long sA, long sB, long sC, int batch,
                        const float* bias,
                        const float* Res, long sRes,
                        float aH, const float* aD, cudaStream_t st)
{
    dim3 grid(N / 128, M / 128, batch);
    dim3 blk(256);
    if (TA == 0 && TB == 0)
        tgemm_kernel<0, 0><<<grid, blk, TSMEM, st>>>(A, B, C, M, N, K, sA, sB, sC, bias, Res, sRes, aH, aD);
    else if (TA == 1 && TB == 0)
        tgemm_kernel<1, 0><<<grid, blk, TSMEM, st>>>(A, B, C, M, N, K, sA, sB, sC, bias, Res, sRes, aH, aD);
    else
        tgemm_kernel<0, 1><<<grid, blk, TSMEM, st>>>(A, B, C, M, N, K, sA, sB, sC, bias, Res, sRes, aH, aD);
}

extern "C" void kernel_launch(void* const* d_in, const int* in_sizes, int n_in,
                              void* d_out, int out_size)
{
    const float* x     = (const float*)d_in[0];
    const float* vfeat = (const float*)d_in[1];
    const float* adj   = (const float*)d_in[2];
    const float* Wq    = (const float*)d_in[3];
    const float* bq    = (const float*)d_in[4];
    const float* Wk    = (const float*)d_in[5];
    const float* bk    = (const float*)d_in[6];
    const float* Wv    = (const float*)d_in[7];
    const float* bv    = (const float*)d_in[8];
    const float* gpam  = (const float*)d_in[9];
    const float* gcam  = (const float*)d_in[10];
    const float* Wg    = (const float*)d_in[11];
    const float* bnw   = (const float*)d_in[12];
    const float* bnb   = (const float*)d_in[13];
    const float* gg    = (const float*)d_in[14];
    float* out = (float*)d_out;

    float *q, *k, *v, *att1, *y1, *h, *ip, *graph, *hp, *gbuf, *mean, *var;
    cudaGetSymbolAddress((void**)&q,    d_q);
    cudaGetSymbolAddress((void**)&k,    d_k);
    cudaGetSymbolAddress((void**)&v,    d_v);
    cudaGetSymbolAddress((void**)&att1, d_att1);
    cudaGetSymbolAddress((void**)&y1,   d_y1);
    cudaGetSymbolAddress((void**)&h,    d_h);
    cudaGetSymbolAddress((void**)&ip,   d_ip);
    cudaGetSymbolAddress((void**)&graph,d_graph);
    cudaGetSymbolAddress((void**)&hp,   d_hp);
    cudaGetSymbolAddress((void**)&gbuf, d_gbuf);
    cudaGetSymbolAddress((void**)&mean, d_mean);
    cudaGetSymbolAddress((void**)&var,  d_var);

    static int inited = 0;
    if (!inited) {
        cudaFuncSetAttribute(tgemm_kernel<0, 0>,
                             cudaFuncAttributeMaxDynamicSharedMemorySize, TSMEM);
        cudaFuncSetAttribute(tgemm_kernel<1, 0>,
                             cudaFuncAttributeMaxDynamicSharedMemorySize, TSMEM);
        cudaFuncSetAttribute(tgemm_kernel<0, 1>,
                             cudaFuncAttributeMaxDynamicSharedMemorySize, TSMEM);
        cudaFuncSetAttribute(cam_tc_kernel,
                             cudaFuncAttributeMaxDynamicSharedMemorySize, CAM_SMEM);
        inited = 1;
    }
    static cudaStream_t s2 = [](){ cudaStream_t s;
        cudaStreamCreateWithFlags(&s, cudaStreamNonBlocking); return s; }();
    static cudaEvent_t evF = [](){ cudaEvent_t e;
        cudaEventCreateWithFlags(&e, cudaEventDisableTiming); return e; }();
    static cudaEvent_t evJ = [](){ cudaEvent_t e;
        cudaEventCreateWithFlags(&e, cudaEventDisableTiming); return e; }();

    const long CHW = (long)CCH * HW;          // 262144
    const long QHW = (long)C8 * HW;           // 32768
    const long GST = (long)VV * CCH;          // 262144
    cudaStream_t s0 = 0;

    // ---- fork ----
    cudaEventRecord(evF, s0);
    cudaStreamWaitEvent(s2, evF, 0);

    // ---------------- PAM (s0) ----------------
    launch_gemm(0, 0, Wq, x, q, C8,  HW, CCH, 0, CHW, QHW, BSZ, bq, nullptr, 0, 1.f, nullptr, s0);
    launch_gemm(0, 0, Wk, x, k, C8,  HW, CCH, 0, CHW, QHW, BSZ, bk, nullptr, 0, 1.f, nullptr, s0);
    launch_gemm(0, 0, Wv, x, v, CCH, HW, CCH, 0, CHW, CHW, BSZ, bv, nullptr, 0, 1.f, nullptr, s0);
    launch_gemm(1, 0, q, k, att1, HW, HW, C8, QHW, QHW, (long)HW * HW, BSZ,
                nullptr, nullptr, 0, 1.f, nullptr, s0);
    softmax_kernel<<<BSZ * HW, 128, 0, s0>>>(att1, HW);
    launch_gemm(0, 1, v, att1, y1, CCH, HW, HW, CHW, (long)HW * HW, CHW, BSZ,
                nullptr, x, CHW, 0.f, gpam, s0);

    // ---------------- CAM (s0, tensor-core flash) ----------------
    {
        dim3 grid(CCH / 128, BSZ);
        cam_tc_kernel<<<grid, 256, CAM_SMEM, s0>>>(y1, gcam, out);
    }

    // ------------- Graph layers (s2) -------------
    const float* inp = vfeat;
    for (int i = 0; i < GNUM; i++) {
        float* outg = (i == GNUM - 1) ? (out + (long)BSZ * CCH * HW) : gbuf;
        launch_gemm(0, 1, inp, Wg + (long)i * CCH * CCH, h,
                    NV * VV, CCH, CCH, 0, 0, 0, 1, nullptr, nullptr, 0, 1.f, nullptr, s2);
        launch_gemm(0, 1, inp, inp, ip, VV, VV, CCH, GST, GST, (long)VV * VV, NV,
                    nullptr, nullptr, 0, 1.f, nullptr, s2);
        graph_build<<<dim3(VV, NV), VV, 0, s2>>>(ip, adj, graph);
        launch_gemm(0, 0, graph, h, hp, VV, CCH, VV, (long)VV * VV, GST, GST, NV,
                    nullptr, nullptr, 0, 1.f, nullptr, s2);
        bn_stats<<<CCH / 32, 256, 0, s2>>>(hp, mean, var, NV * VV, CCH);
        bn_apply<<<(NV * VV * CCH + 255) / 256, 256, 0, s2>>>(
            inp, hp, mean, var, bnw + (long)i * CCH, bnb + (long)i * CCH,
            gg + i, outg, NV * VV * CCH, CCH);
        inp = outg;
    }

    // ---- join ----
    cudaEventRecord(evJ, s2);
    cudaStreamWaitEvent(s0, evJ, 0);
}